// round 1
// baseline (speedup 1.0000x reference)
#include <cuda_runtime.h>
#include <math.h>

#define S_  1024
#define B_  128
#define F_  202
#define H_  100
#define K_  19
#define N2_ 200   // 2*H

// ---- scratch (device globals: no runtime allocation allowed) ----
__device__ float g_xp[(size_t)S_ * B_ * N2_];  // input projections, both dirs
__device__ float g_h [(size_t)S_ * B_ * N2_];  // hidden states [hf | hb]
__device__ float g_em[(size_t)S_ * B_ * K_];   // softmax emissions

// =====================================================================
// Kernel 1: input projection  xp = x @ W_ih^T + b_ih + b_hh  (both dirs)
//   C(M=131072, N=200) = A(M,202) * B(200,202)^T
//   Tile: 64 rows x 200 cols, full K in SMEM, 320 threads, 4x10 micro-tile
// =====================================================================
#define PJ_BM   64
#define PJ_FP   204              // F padded to multiple of 4 (zero-filled)
#define PJ_AS4  53               // A row stride (float4) -> 212 floats
#define PJ_BS4  51               // B row stride (float4) -> 204 floats
#define PJ_A_F4 (PJ_BM * PJ_AS4) // 3392
#define PJ_B_F4 (N2_ * PJ_BS4)   // 10200
#define PJ_SMEM ((PJ_A_F4 + PJ_B_F4) * 16)  // 217472 bytes

__global__ __launch_bounds__(320, 1) void proj_kernel(
    const float* __restrict__ x,
    const float* __restrict__ Wf, const float* __restrict__ Wb,
    const float* __restrict__ bihf, const float* __restrict__ bhhf,
    const float* __restrict__ bihb, const float* __restrict__ bhhb)
{
    extern __shared__ float4 sm4[];
    float* Ash = (float*)sm4;                  // [64][212]
    float* Bsh = (float*)(sm4 + PJ_A_F4);      // [200][204]
    const int tid = threadIdx.x;
    const int m0  = blockIdx.x * PJ_BM;

    // stage A tile (zero-pad f>=202)
    for (int e = tid; e < PJ_BM * PJ_FP; e += 320) {
        int r = e / PJ_FP, f = e - r * PJ_FP;
        Ash[r * (PJ_AS4 * 4) + f] = (f < F_) ? x[(size_t)(m0 + r) * F_ + f] : 0.f;
    }
    // stage B tile (both direction weight matrices stacked)
    for (int e = tid; e < N2_ * PJ_FP; e += 320) {
        int n = e / PJ_FP, f = e - n * PJ_FP;
        float v = 0.f;
        if (f < F_) v = (n < H_) ? Wf[n * F_ + f] : Wb[(n - H_) * F_ + f];
        Bsh[n * PJ_FP + f] = v;
    }
    __syncthreads();

    const int tx = tid & 15;    // row group (strided rows)
    const int ty = tid >> 4;    // col group 0..19
    const float4* A4 = sm4;
    const float4* B4 = sm4 + PJ_A_F4;

    float acc[4][10];
    #pragma unroll
    for (int i = 0; i < 4; i++)
        #pragma unroll
        for (int j = 0; j < 10; j++) acc[i][j] = 0.f;

    for (int kk = 0; kk < 51; kk++) {
        float4 a[4], b[10];
        #pragma unroll
        for (int i = 0; i < 4; i++) a[i] = A4[(tx + 16 * i) * PJ_AS4 + kk];
        #pragma unroll
        for (int j = 0; j < 10; j++) b[j] = B4[(ty + 20 * j) * PJ_BS4 + kk];
        #pragma unroll
        for (int i = 0; i < 4; i++)
            #pragma unroll
            for (int j = 0; j < 10; j++) {
                acc[i][j] += a[i].x * b[j].x;
                acc[i][j] += a[i].y * b[j].y;
                acc[i][j] += a[i].z * b[j].z;
                acc[i][j] += a[i].w * b[j].w;
            }
    }

    #pragma unroll
    for (int j = 0; j < 10; j++) {
        int n = ty + 20 * j;
        float bias = (n < H_) ? (bihf[n] + bhhf[n]) : (bihb[n - H_] + bhhb[n - H_]);
        #pragma unroll
        for (int i = 0; i < 4; i++) {
            int m = m0 + tx + 16 * i;
            g_xp[(size_t)m * N2_ + n] = acc[i][j] + bias;
        }
    }
}

// =====================================================================
// Kernel 2: recurrent scans. One CTA per (direction, batch) chain.
//   h_t = tanh(xp_t + W_hh @ h_{t-1}); W_hh row held in registers.
// =====================================================================
__global__ __launch_bounds__(128) void rnn_kernel(
    const float* __restrict__ Whhf, const float* __restrict__ Whhb)
{
    const int chain = blockIdx.x;        // 0..255
    const int dir   = chain >> 7;        // 0 fwd, 1 bwd
    const int b     = chain & 127;
    const int j     = threadIdx.x;       // 0..127 (j<100 active)

    __shared__ __align__(16) float hs[2][104];

    const float* Whh = dir ? Whhb : Whhf;
    float4 w4[25];
    if (j < H_) {
        const float4* wp = (const float4*)(Whh + j * H_);  // row is 400B, 16B-aligned
        #pragma unroll
        for (int k = 0; k < 25; k++) w4[k] = wp[k];
    }
    if (j < 104) { hs[0][j] = 0.f; hs[1][j] = 0.f; }
    __syncthreads();

    const float* xpb = g_xp + (size_t)b * N2_ + dir * H_ + j;
    float*       hgb = g_h  + (size_t)b * N2_ + dir * H_ + j;
    const int s0 = dir ? (S_ - 1) : 0;
    const int ds = dir ? -1 : 1;
    const int STRIDE = B_ * N2_;  // 25600

    int p = 0;
    float xv = (j < H_) ? xpb[(size_t)s0 * STRIDE] : 0.f;  // prefetch t=0

    for (int t = 0; t < S_; t++) {
        const int s = s0 + ds * t;
        float acc = xv;
        if (t + 1 < S_ && j < H_) xv = xpb[(size_t)(s + ds) * STRIDE];  // prefetch next

        if (j < H_) {
            const float4* hv4 = (const float4*)hs[p];
            #pragma unroll
            for (int k = 0; k < 25; k++) {
                float4 h4 = hv4[k];
                acc += w4[k].x * h4.x;
                acc += w4[k].y * h4.y;
                acc += w4[k].z * h4.z;
                acc += w4[k].w * h4.w;
            }
            float hn = tanhf(acc);
            hs[p ^ 1][j] = hn;
            hgb[(size_t)s * STRIDE] = hn;
        }
        __syncthreads();
        p ^= 1;
    }
}

// =====================================================================
// Kernel 3: logits + softmax -> emissions. Thread per (s,b) row.
// =====================================================================
__global__ __launch_bounds__(256) void logits_kernel(
    const float* __restrict__ Wout, const float* __restrict__ bout)
{
    __shared__ float wt[N2_ * 20];   // W_out transposed, K padded 19->20
    const int tid = threadIdx.x;
    for (int e = tid; e < N2_ * 20; e += 256) {
        int f = e / 20, k = e - f * 20;
        wt[e] = (k < K_) ? Wout[k * N2_ + f] : 0.f;
    }
    __syncthreads();

    const int m = blockIdx.x * 256 + tid;     // row index, always < 131072
    const float4* hp  = (const float4*)(g_h + (size_t)m * N2_);
    const float4* wt4 = (const float4*)wt;

    float acc[20];
    #pragma unroll
    for (int k = 0; k < 20; k++) acc[k] = 0.f;

    for (int f4 = 0; f4 < 50; f4++) {
        float4 hv = __ldg(&hp[f4]);
        float hh[4] = {hv.x, hv.y, hv.z, hv.w};
        #pragma unroll
        for (int c = 0; c < 4; c++) {
            const int f = f4 * 4 + c;
            #pragma unroll
            for (int q = 0; q < 5; q++) {
                float4 wv = wt4[f * 5 + q];
                acc[q * 4 + 0] += hh[c] * wv.x;
                acc[q * 4 + 1] += hh[c] * wv.y;
                acc[q * 4 + 2] += hh[c] * wv.z;
                acc[q * 4 + 3] += hh[c] * wv.w;
            }
        }
    }

    float mx = -1e30f;
    #pragma unroll
    for (int k = 0; k < K_; k++) { acc[k] += __ldg(&bout[k]); mx = fmaxf(mx, acc[k]); }
    float sum = 0.f;
    #pragma unroll
    for (int k = 0; k < K_; k++) { acc[k] = __expf(acc[k] - mx); sum += acc[k]; }
    const float inv = 1.f / sum;
    float* e = g_em + (size_t)m * K_;
    #pragma unroll
    for (int k = 0; k < K_; k++) e[k] = acc[k] * inv;
}

// =====================================================================
// Kernel 4: Viterbi decode. Warp per sequence (n = s index, T = B steps).
//   lane j tracks tag j; scores exchanged with shuffles; first-max ties.
// =====================================================================
__global__ __launch_bounds__(256) void viterbi_kernel(
    const float* __restrict__ start, const float* __restrict__ endt,
    const float* __restrict__ trans, float* __restrict__ out)
{
    __shared__ unsigned char hist[8][127][20];
    const int w    = threadIdx.x >> 5;
    const int lane = threadIdx.x & 31;
    const int n    = blockIdx.x * 8 + w;       // sequence index 0..1023
    const int j    = lane;
    const bool act = (j < K_);

    float tr[K_];
    #pragma unroll
    for (int i = 0; i < K_; i++) tr[i] = act ? trans[i * K_ + j] : 0.f;

    const float* emn = g_em + (size_t)n * B_ * K_;
    float score = act ? (start[j] + emn[j]) : -1e30f;

    for (int t = 1; t < B_; t++) {
        const float e = act ? emn[t * K_ + j] : 0.f;
        float best = -1e30f; int bi = 0;
        #pragma unroll
        for (int i = 0; i < K_; i++) {
            float si = __shfl_sync(0xffffffffu, score, i);
            float v  = si + tr[i];
            if (v > best) { best = v; bi = i; }   // strict > => first max (jnp.argmax)
        }
        if (act) hist[w][t - 1][j] = (unsigned char)bi;
        score = best + e;
    }

    // final argmax over tags (first-max tie-break)
    float v  = act ? (score + endt[j]) : -1e30f;
    int  idx = j;
    #pragma unroll
    for (int off = 16; off; off >>= 1) {
        float ov = __shfl_down_sync(0xffffffffu, v, off);
        int   oi = __shfl_down_sync(0xffffffffu, idx, off);
        if (ov > v || (ov == v && oi < idx)) { v = ov; idx = oi; }
    }
    __syncwarp();  // make hist writes visible to lane 0

    if (lane == 0) {
        int tag = idx;
        float* o = out + (size_t)n * B_;
        o[B_ - 1] = (float)tag;
        for (int t = B_ - 2; t >= 0; t--) {
            tag  = hist[w][t][tag];
            o[t] = (float)tag;
        }
    }
}

// =====================================================================
extern "C" void kernel_launch(void* const* d_in, const int* in_sizes, int n_in,
                              void* d_out, int out_size)
{
    const float* x     = (const float*)d_in[0];
    const float* Wihf  = (const float*)d_in[1];
    const float* Whhf  = (const float*)d_in[2];
    const float* bihf  = (const float*)d_in[3];
    const float* bhhf  = (const float*)d_in[4];
    const float* Wihb  = (const float*)d_in[5];
    const float* Whhb  = (const float*)d_in[6];
    const float* bihb  = (const float*)d_in[7];
    const float* bhhb  = (const float*)d_in[8];
    const float* Wout  = (const float*)d_in[9];
    const float* bout  = (const float*)d_in[10];
    const float* start = (const float*)d_in[11];
    const float* endt  = (const float*)d_in[12];
    const float* trans = (const float*)d_in[13];
    float* out = (float*)d_out;

    cudaFuncSetAttribute(proj_kernel, cudaFuncAttributeMaxDynamicSharedMemorySize, PJ_SMEM);

    proj_kernel<<<(S_ * B_) / PJ_BM, 320, PJ_SMEM>>>(x, Wihf, Wihb, bihf, bhhf, bihb, bhhb);
    rnn_kernel<<<2 * B_, 128>>>(Whhf, Whhb);
    logits_kernel<<<(S_ * B_) / 256, 256>>>(Wout, bout);
    viterbi_kernel<<<S_ / 8, 256>>>(start, endt, trans, out);
}

// round 2
// speedup vs baseline: 1.0086x; 1.0086x over previous
#include <cuda_runtime.h>
#include <math.h>

#define S_  1024
#define B_  128
#define F_  202
#define H_  100
#define K_  19
#define N2_ 200   // 2*H

// ---- scratch (device globals: no runtime allocation allowed) ----
__device__ float g_xp[(size_t)S_ * B_ * N2_];  // input projections, both dirs
__device__ float g_h [(size_t)S_ * B_ * N2_];  // hidden states [hf | hb]
__device__ float g_em[(size_t)S_ * B_ * K_];   // softmax emissions

// ---- packed dual-fp32 FMA helpers (sm_103a f32x2 pipe) ----
static __device__ __forceinline__ unsigned long long ffma2_(
    unsigned long long a, unsigned long long b, unsigned long long c)
{
    unsigned long long d;
    asm("fma.rn.f32x2 %0, %1, %2, %3;" : "=l"(d) : "l"(a), "l"(b), "l"(c));
    return d;
}
static __device__ __forceinline__ float lo_(unsigned long long v) {
    return __uint_as_float((unsigned)(v & 0xffffffffull));
}
static __device__ __forceinline__ float hi_(unsigned long long v) {
    return __uint_as_float((unsigned)(v >> 32));
}
static __device__ __forceinline__ unsigned long long pack2_(float lo, float hi) {
    unsigned long long r;
    asm("mov.b64 %0, {%1, %2};" : "=l"(r) : "f"(lo), "f"(hi));
    return r;
}

// =====================================================================
// Kernel 1: input projection  xp = x @ W_ih^T + b_ih + b_hh  (both dirs)
//   C(M=131072, N=200) = A(M,202) * B(200,202)^T
//   Tile: 64 rows x 200 cols, full K in SMEM, 320 threads, 4x10 micro-tile
//   Inner product done with packed f32x2 FMA (2 MACs / instr).
// =====================================================================
#define PJ_BM   64
#define PJ_FP   204              // F padded to multiple of 4 (zero-filled)
#define PJ_AS4  53               // A row stride (16B units) -> 212 floats
#define PJ_BS4  51               // B row stride (16B units) -> 204 floats
#define PJ_A_F4 (PJ_BM * PJ_AS4) // 3392
#define PJ_B_F4 (N2_ * PJ_BS4)   // 10200
#define PJ_SMEM ((PJ_A_F4 + PJ_B_F4) * 16)  // 217472 bytes

__global__ __launch_bounds__(320, 1) void proj_kernel(
    const float* __restrict__ x,
    const float* __restrict__ Wf, const float* __restrict__ Wb,
    const float* __restrict__ bihf, const float* __restrict__ bhhf,
    const float* __restrict__ bihb, const float* __restrict__ bhhb)
{
    extern __shared__ ulonglong2 sm2[];
    float* Ash = (float*)sm2;                  // [64][212]
    float* Bsh = (float*)(sm2 + PJ_A_F4);      // [200][204]
    const int tid = threadIdx.x;
    const int m0  = blockIdx.x * PJ_BM;

    // stage A tile (zero-pad f>=202)
    for (int e = tid; e < PJ_BM * PJ_FP; e += 320) {
        int r = e / PJ_FP, f = e - r * PJ_FP;
        Ash[r * (PJ_AS4 * 4) + f] = (f < F_) ? x[(size_t)(m0 + r) * F_ + f] : 0.f;
    }
    // stage B tile (both direction weight matrices stacked)
    for (int e = tid; e < N2_ * PJ_FP; e += 320) {
        int n = e / PJ_FP, f = e - n * PJ_FP;
        float v = 0.f;
        if (f < F_) v = (n < H_) ? Wf[n * F_ + f] : Wb[(n - H_) * F_ + f];
        Bsh[n * PJ_FP + f] = v;
    }
    __syncthreads();

    const int tx = tid & 15;    // row group (strided rows)
    const int ty = tid >> 4;    // col group 0..19
    const ulonglong2* A2 = sm2;
    const ulonglong2* B2 = sm2 + PJ_A_F4;

    unsigned long long acc2[4][10];
    #pragma unroll
    for (int i = 0; i < 4; i++)
        #pragma unroll
        for (int j = 0; j < 10; j++) acc2[i][j] = 0ull;

    for (int kk = 0; kk < 51; kk++) {
        ulonglong2 a[4], b[10];
        #pragma unroll
        for (int i = 0; i < 4; i++) a[i] = A2[(tx + 16 * i) * PJ_AS4 + kk];
        #pragma unroll
        for (int j = 0; j < 10; j++) b[j] = B2[(ty + 20 * j) * PJ_BS4 + kk];
        #pragma unroll
        for (int i = 0; i < 4; i++)
            #pragma unroll
            for (int j = 0; j < 10; j++) {
                acc2[i][j] = ffma2_(a[i].x, b[j].x, acc2[i][j]);
                acc2[i][j] = ffma2_(a[i].y, b[j].y, acc2[i][j]);
            }
    }

    #pragma unroll
    for (int j = 0; j < 10; j++) {
        int n = ty + 20 * j;
        float bias = (n < H_) ? (bihf[n] + bhhf[n]) : (bihb[n - H_] + bhhb[n - H_]);
        #pragma unroll
        for (int i = 0; i < 4; i++) {
            int m = m0 + tx + 16 * i;
            g_xp[(size_t)m * N2_ + n] = lo_(acc2[i][j]) + hi_(acc2[i][j]) + bias;
        }
    }
}

// =====================================================================
// Kernel 2: recurrent scans. One CTA per (direction, batch) chain.
//   h_t = tanh(xp_t + W_hh @ h_{t-1}); W_hh row in registers (packed),
//   4 packed accumulators -> dependent-FMA chain ~13 deep (was 100).
// =====================================================================
__global__ __launch_bounds__(128) void rnn_kernel(
    const float* __restrict__ Whhf, const float* __restrict__ Whhb)
{
    const int chain = blockIdx.x;        // 0..255
    const int dir   = chain >> 7;        // 0 fwd, 1 bwd
    const int b     = chain & 127;
    const int j     = threadIdx.x;       // 0..127 (j<100 active)

    __shared__ __align__(16) float hs[2][104];

    const float* Whh = dir ? Whhb : Whhf;
    unsigned long long w2[50];
    if (j < H_) {
        const ulonglong2* wp = (const ulonglong2*)(Whh + j * H_);  // 400B rows, 16B-aligned
        #pragma unroll
        for (int k = 0; k < 25; k++) { ulonglong2 t = wp[k]; w2[2*k] = t.x; w2[2*k+1] = t.y; }
    }
    if (j < 104) { hs[0][j] = 0.f; hs[1][j] = 0.f; }
    __syncthreads();

    const float* xpb = g_xp + (size_t)b * N2_ + dir * H_ + j;
    float*       hgb = g_h  + (size_t)b * N2_ + dir * H_ + j;
    const int s0 = dir ? (S_ - 1) : 0;
    const int ds = dir ? -1 : 1;
    const int STRIDE = B_ * N2_;  // 25600

    int p = 0;
    float xv = (j < H_) ? xpb[(size_t)s0 * STRIDE] : 0.f;  // prefetch t=0

    for (int t = 0; t < S_; t++) {
        const int s = s0 + ds * t;
        float x0 = xv;
        if (t + 1 < S_ && j < H_) xv = xpb[(size_t)(s + ds) * STRIDE];  // prefetch next

        if (j < H_) {
            const ulonglong2* hv2 = (const ulonglong2*)hs[p];
            unsigned long long a0 = 0ull, a1 = 0ull, a2 = 0ull, a3 = 0ull;
            #pragma unroll
            for (int k = 0; k < 25; k += 2) {
                ulonglong2 h2 = hv2[k];
                a0 = ffma2_(w2[2*k],   h2.x, a0);
                a1 = ffma2_(w2[2*k+1], h2.y, a1);
                if (k + 1 < 25) {
                    ulonglong2 g2 = hv2[k + 1];
                    a2 = ffma2_(w2[2*k+2], g2.x, a2);
                    a3 = ffma2_(w2[2*k+3], g2.y, a3);
                }
            }
            float acc = x0 + ((lo_(a0) + hi_(a0)) + (lo_(a1) + hi_(a1)))
                           + ((lo_(a2) + hi_(a2)) + (lo_(a3) + hi_(a3)));
            float hn = tanhf(acc);
            hs[p ^ 1][j] = hn;
            hgb[(size_t)s * STRIDE] = hn;
        }
        __syncthreads();
        p ^= 1;
    }
}

// =====================================================================
// Kernel 3: logits + softmax -> emissions. Thread per (s,b) row.
//   Packed f32x2 over tag pairs (K padded 19->20 => 10 packed accs).
// =====================================================================
__global__ __launch_bounds__(256) void logits_kernel(
    const float* __restrict__ Wout, const float* __restrict__ bout)
{
    __shared__ __align__(16) float wt[N2_ * 20];   // W_out^T, K padded 19->20
    const int tid = threadIdx.x;
    for (int e = tid; e < N2_ * 20; e += 256) {
        int f = e / 20, k = e - f * 20;
        wt[e] = (k < K_) ? Wout[k * N2_ + f] : 0.f;
    }
    __syncthreads();

    const int m = blockIdx.x * 256 + tid;     // row index, always < 131072
    const float4* hp = (const float4*)(g_h + (size_t)m * N2_);
    const ulonglong2* wt2 = (const ulonglong2*)wt;   // [f][5] of (k-pair, k-pair)

    unsigned long long acc2[10];
    #pragma unroll
    for (int q = 0; q < 10; q++) acc2[q] = 0ull;

    for (int f4 = 0; f4 < 50; f4++) {
        float4 hv = __ldg(&hp[f4]);
        float hh[4] = {hv.x, hv.y, hv.z, hv.w};
        #pragma unroll
        for (int c = 0; c < 4; c++) {
            const int f = f4 * 4 + c;
            const unsigned long long hb = pack2_(hh[c], hh[c]);
            #pragma unroll
            for (int q = 0; q < 5; q++) {
                ulonglong2 wv = wt2[f * 5 + q];
                acc2[2*q]     = ffma2_(hb, wv.x, acc2[2*q]);
                acc2[2*q + 1] = ffma2_(hb, wv.y, acc2[2*q + 1]);
            }
        }
    }

    float acc[20];
    #pragma unroll
    for (int q = 0; q < 10; q++) { acc[2*q] = lo_(acc2[q]); acc[2*q+1] = hi_(acc2[q]); }

    float mx = -1e30f;
    #pragma unroll
    for (int k = 0; k < K_; k++) { acc[k] += __ldg(&bout[k]); mx = fmaxf(mx, acc[k]); }
    float sum = 0.f;
    #pragma unroll
    for (int k = 0; k < K_; k++) { acc[k] = __expf(acc[k] - mx); sum += acc[k]; }
    const float inv = 1.f / sum;
    float* e = g_em + (size_t)m * K_;
    #pragma unroll
    for (int k = 0; k < K_; k++) e[k] = acc[k] * inv;
}

// =====================================================================
// Kernel 4: Viterbi decode. Warp per sequence (n = s index, T = B steps).
//   lane j tracks tag j; scores exchanged with shuffles; first-max ties.
// =====================================================================
__global__ __launch_bounds__(256) void viterbi_kernel(
    const float* __restrict__ start, const float* __restrict__ endt,
    const float* __restrict__ trans, float* __restrict__ out)
{
    __shared__ unsigned char hist[8][127][20];
    const int w    = threadIdx.x >> 5;
    const int lane = threadIdx.x & 31;
    const int n    = blockIdx.x * 8 + w;       // sequence index 0..1023
    const int j    = lane;
    const bool act = (j < K_);

    float tr[K_];
    #pragma unroll
    for (int i = 0; i < K_; i++) tr[i] = act ? trans[i * K_ + j] : 0.f;

    const float* emn = g_em + (size_t)n * B_ * K_;
    float score = act ? (start[j] + emn[j]) : -1e30f;

    for (int t = 1; t < B_; t++) {
        const float e = act ? emn[t * K_ + j] : 0.f;
        float best = -1e30f; int bi = 0;
        #pragma unroll
        for (int i = 0; i < K_; i++) {
            float si = __shfl_sync(0xffffffffu, score, i);
            float v  = si + tr[i];
            if (v > best) { best = v; bi = i; }   // strict > => first max (jnp.argmax)
        }
        if (act) hist[w][t - 1][j] = (unsigned char)bi;
        score = best + e;
    }

    // final argmax over tags (first-max tie-break)
    float v  = act ? (score + endt[j]) : -1e30f;
    int  idx = j;
    #pragma unroll
    for (int off = 16; off; off >>= 1) {
        float ov = __shfl_down_sync(0xffffffffu, v, off);
        int   oi = __shfl_down_sync(0xffffffffu, idx, off);
        if (ov > v || (ov == v && oi < idx)) { v = ov; idx = oi; }
    }
    __syncwarp();  // make hist writes visible to lane 0

    if (lane == 0) {
        int tag = idx;
        float* o = out + (size_t)n * B_;
        o[B_ - 1] = (float)tag;
        for (int t = B_ - 2; t >= 0; t--) {
            tag  = hist[w][t][tag];
            o[t] = (float)tag;
        }
    }
}

// =====================================================================
extern "C" void kernel_launch(void* const* d_in, const int* in_sizes, int n_in,
                              void* d_out, int out_size)
{
    const float* x     = (const float*)d_in[0];
    const float* Wihf  = (const float*)d_in[1];
    const float* Whhf  = (const float*)d_in[2];
    const float* bihf  = (const float*)d_in[3];
    const float* bhhf  = (const float*)d_in[4];
    const float* Wihb  = (const float*)d_in[5];
    const float* Whhb  = (const float*)d_in[6];
    const float* bihb  = (const float*)d_in[7];
    const float* bhhb  = (const float*)d_in[8];
    const float* Wout  = (const float*)d_in[9];
    const float* bout  = (const float*)d_in[10];
    const float* start = (const float*)d_in[11];
    const float* endt  = (const float*)d_in[12];
    const float* trans = (const float*)d_in[13];
    float* out = (float*)d_out;

    cudaFuncSetAttribute(proj_kernel, cudaFuncAttributeMaxDynamicSharedMemorySize, PJ_SMEM);

    proj_kernel<<<(S_ * B_) / PJ_BM, 320, PJ_SMEM>>>(x, Wihf, Wihb, bihf, bhhf, bihb, bhhb);
    rnn_kernel<<<2 * B_, 128>>>(Whhf, Whhb);
    logits_kernel<<<(S_ * B_) / 256, 256>>>(Wout, bout);
    viterbi_kernel<<<S_ / 8, 256>>>(start, endt, trans, out);
}

// round 3
// speedup vs baseline: 1.0403x; 1.0314x over previous
#include <cuda_runtime.h>
#include <math.h>

#define S_  1024
#define B_  128
#define F_  202
#define H_  100
#define K_  19
#define N2_ 200   // 2*H

// ---- scratch (device globals: no runtime allocation allowed) ----
__device__ float g_xp[(size_t)S_ * B_ * N2_];  // input projections, both dirs
__device__ float g_h [(size_t)S_ * B_ * N2_];  // hidden states [hf | hb]
__device__ float g_em[(size_t)S_ * B_ * K_];   // softmax emissions

// ---- packed dual-fp32 FMA helpers (sm_103a f32x2 pipe) ----
static __device__ __forceinline__ unsigned long long ffma2_(
    unsigned long long a, unsigned long long b, unsigned long long c)
{
    unsigned long long d;
    asm("fma.rn.f32x2 %0, %1, %2, %3;" : "=l"(d) : "l"(a), "l"(b), "l"(c));
    return d;
}
static __device__ __forceinline__ float lo_(unsigned long long v) {
    return __uint_as_float((unsigned)(v & 0xffffffffull));
}
static __device__ __forceinline__ float hi_(unsigned long long v) {
    return __uint_as_float((unsigned)(v >> 32));
}
static __device__ __forceinline__ unsigned long long pack2_(float lo, float hi) {
    unsigned long long r;
    asm("mov.b64 %0, {%1, %2};" : "=l"(r) : "f"(lo), "f"(hi));
    return r;
}

// profiling-slot spacer (ncu captures the 4th app launch; make it rnn)
__global__ void noop_kernel() {}

// =====================================================================
// Kernel 1: input projection  xp = x @ W_ih^T + b_ih + b_hh  (both dirs)
// =====================================================================
#define PJ_BM   64
#define PJ_FP   204              // F padded to multiple of 4 (zero-filled)
#define PJ_AS4  53               // A row stride (16B units) -> 212 floats
#define PJ_BS4  51               // B row stride (16B units) -> 204 floats
#define PJ_A_F4 (PJ_BM * PJ_AS4) // 3392
#define PJ_B_F4 (N2_ * PJ_BS4)   // 10200
#define PJ_SMEM ((PJ_A_F4 + PJ_B_F4) * 16)  // 217472 bytes

__global__ __launch_bounds__(320, 1) void proj_kernel(
    const float* __restrict__ x,
    const float* __restrict__ Wf, const float* __restrict__ Wb,
    const float* __restrict__ bihf, const float* __restrict__ bhhf,
    const float* __restrict__ bihb, const float* __restrict__ bhhb)
{
    extern __shared__ ulonglong2 sm2[];
    float* Ash = (float*)sm2;                  // [64][212]
    float* Bsh = (float*)(sm2 + PJ_A_F4);      // [200][204]
    const int tid = threadIdx.x;
    const int m0  = blockIdx.x * PJ_BM;

    for (int e = tid; e < PJ_BM * PJ_FP; e += 320) {
        int r = e / PJ_FP, f = e - r * PJ_FP;
        Ash[r * (PJ_AS4 * 4) + f] = (f < F_) ? x[(size_t)(m0 + r) * F_ + f] : 0.f;
    }
    for (int e = tid; e < N2_ * PJ_FP; e += 320) {
        int n = e / PJ_FP, f = e - n * PJ_FP;
        float v = 0.f;
        if (f < F_) v = (n < H_) ? Wf[n * F_ + f] : Wb[(n - H_) * F_ + f];
        Bsh[n * PJ_FP + f] = v;
    }
    __syncthreads();

    const int tx = tid & 15;    // row group (strided rows)
    const int ty = tid >> 4;    // col group 0..19
    const ulonglong2* A2 = sm2;
    const ulonglong2* B2 = sm2 + PJ_A_F4;

    unsigned long long acc2[4][10];
    #pragma unroll
    for (int i = 0; i < 4; i++)
        #pragma unroll
        for (int j = 0; j < 10; j++) acc2[i][j] = 0ull;

    for (int kk = 0; kk < 51; kk++) {
        ulonglong2 a[4], b[10];
        #pragma unroll
        for (int i = 0; i < 4; i++) a[i] = A2[(tx + 16 * i) * PJ_AS4 + kk];
        #pragma unroll
        for (int j = 0; j < 10; j++) b[j] = B2[(ty + 20 * j) * PJ_BS4 + kk];
        #pragma unroll
        for (int i = 0; i < 4; i++)
            #pragma unroll
            for (int j = 0; j < 10; j++) {
                acc2[i][j] = ffma2_(a[i].x, b[j].x, acc2[i][j]);
                acc2[i][j] = ffma2_(a[i].y, b[j].y, acc2[i][j]);
            }
    }

    #pragma unroll
    for (int j = 0; j < 10; j++) {
        int n = ty + 20 * j;
        float bias = (n < H_) ? (bihf[n] + bhhf[n]) : (bihb[n - H_] + bhhb[n - H_]);
        #pragma unroll
        for (int i = 0; i < 4; i++) {
            int m = m0 + tx + 16 * i;
            g_xp[(size_t)m * N2_ + n] = lo_(acc2[i][j]) + hi_(acc2[i][j]) + bias;
        }
    }
}

// =====================================================================
// Kernel 2: recurrent scans. One CTA per (direction, batch) chain.
//   h_t = tanh(xp_t + W_hh @ h_{t-1}); W_hh row in registers (packed).
//   4-deep xp prefetch queue (MLP=4 hides DRAM), fast inf-safe tanh.
// =====================================================================
__global__ __launch_bounds__(128) void rnn_kernel(
    const float* __restrict__ Whhf, const float* __restrict__ Whhb)
{
    const int chain = blockIdx.x;        // 0..255
    const int dir   = chain >> 7;        // 0 fwd, 1 bwd
    const int b     = chain & 127;
    const int j     = threadIdx.x;       // 0..127 (j<100 active)

    __shared__ __align__(16) float hs[2][104];

    const float* Whh = dir ? Whhb : Whhf;
    unsigned long long w2[50];
    if (j < H_) {
        const ulonglong2* wp = (const ulonglong2*)(Whh + j * H_);
        #pragma unroll
        for (int k = 0; k < 25; k++) { ulonglong2 t = wp[k]; w2[2*k] = t.x; w2[2*k+1] = t.y; }
    }
    if (j < 104) { hs[0][j] = 0.f; hs[1][j] = 0.f; }
    __syncthreads();

    const float* xpb = g_xp + (size_t)b * N2_ + dir * H_ + j;
    float*       hgb = g_h  + (size_t)b * N2_ + dir * H_ + j;
    const int s0 = dir ? (S_ - 1) : 0;
    const int ds = dir ? -1 : 1;
    const int STRIDE = B_ * N2_;  // 25600

    // 4-deep prefetch queue of xp values (independent loads in flight)
    float xq[4];
    if (j < H_) {
        #pragma unroll
        for (int q = 0; q < 4; q++) xq[q] = xpb[(size_t)(s0 + ds * q) * STRIDE];
    } else {
        xq[0] = xq[1] = xq[2] = xq[3] = 0.f;
    }

    int p = 0;
    #pragma unroll 4
    for (int t = 0; t < S_; t++) {
        const int s = s0 + ds * t;
        const float x0 = xq[t & 3];
        if (j < H_ && t + 4 < S_) xq[t & 3] = xpb[(size_t)(s0 + ds * (t + 4)) * STRIDE];

        if (j < H_) {
            const ulonglong2* hv2 = (const ulonglong2*)hs[p];
            unsigned long long a0 = 0ull, a1 = 0ull, a2 = 0ull, a3 = 0ull;
            #pragma unroll
            for (int k = 0; k < 25; k += 2) {
                ulonglong2 h2 = hv2[k];
                a0 = ffma2_(w2[2*k],   h2.x, a0);
                a1 = ffma2_(w2[2*k+1], h2.y, a1);
                if (k + 1 < 25) {
                    ulonglong2 g2 = hv2[k + 1];
                    a2 = ffma2_(w2[2*k+2], g2.x, a2);
                    a3 = ffma2_(w2[2*k+3], g2.y, a3);
                }
            }
            float acc = x0 + ((lo_(a0) + hi_(a0)) + (lo_(a1) + hi_(a1)))
                           + ((lo_(a2) + hi_(a2)) + (lo_(a3) + hi_(a3)));
            // tanh(x) = 1 - 2/(e^{2x}+1); inf-safe both directions, ~1e-7 abs err
            float e2 = __expf(acc + acc);
            float hn = 1.f - __fdividef(2.f, e2 + 1.f);
            hs[p ^ 1][j] = hn;
            hgb[(size_t)s * STRIDE] = hn;
        }
        __syncthreads();
        p ^= 1;
    }
}

// =====================================================================
// Kernel 3: logits + softmax -> emissions. Thread per (s,b) row.
// =====================================================================
__global__ __launch_bounds__(256) void logits_kernel(
    const float* __restrict__ Wout, const float* __restrict__ bout)
{
    __shared__ __align__(16) float wt[N2_ * 20];   // W_out^T, K padded 19->20
    const int tid = threadIdx.x;
    for (int e = tid; e < N2_ * 20; e += 256) {
        int f = e / 20, k = e - f * 20;
        wt[e] = (k < K_) ? Wout[k * N2_ + f] : 0.f;
    }
    __syncthreads();

    const int m = blockIdx.x * 256 + tid;     // row index, always < 131072
    const float4* hp = (const float4*)(g_h + (size_t)m * N2_);
    const ulonglong2* wt2 = (const ulonglong2*)wt;   // [f][5] of (k-pair, k-pair)

    unsigned long long acc2[10];
    #pragma unroll
    for (int q = 0; q < 10; q++) acc2[q] = 0ull;

    for (int f4 = 0; f4 < 50; f4++) {
        float4 hv = __ldg(&hp[f4]);
        float hh[4] = {hv.x, hv.y, hv.z, hv.w};
        #pragma unroll
        for (int c = 0; c < 4; c++) {
            const int f = f4 * 4 + c;
            const unsigned long long hb = pack2_(hh[c], hh[c]);
            #pragma unroll
            for (int q = 0; q < 5; q++) {
                ulonglong2 wv = wt2[f * 5 + q];
                acc2[2*q]     = ffma2_(hb, wv.x, acc2[2*q]);
                acc2[2*q + 1] = ffma2_(hb, wv.y, acc2[2*q + 1]);
            }
        }
    }

    float acc[20];
    #pragma unroll
    for (int q = 0; q < 10; q++) { acc[2*q] = lo_(acc2[q]); acc[2*q+1] = hi_(acc2[q]); }

    float mx = -1e30f;
    #pragma unroll
    for (int k = 0; k < K_; k++) { acc[k] += __ldg(&bout[k]); mx = fmaxf(mx, acc[k]); }
    float sum = 0.f;
    #pragma unroll
    for (int k = 0; k < K_; k++) { acc[k] = __expf(acc[k] - mx); sum += acc[k]; }
    const float inv = 1.f / sum;
    float* e = g_em + (size_t)m * K_;
    #pragma unroll
    for (int k = 0; k < K_; k++) e[k] = acc[k] * inv;
}

// =====================================================================
// Kernel 4: Viterbi decode. Warp per sequence (n = s index, T = B steps).
// =====================================================================
__global__ __launch_bounds__(256) void viterbi_kernel(
    const float* __restrict__ start, const float* __restrict__ endt,
    const float* __restrict__ trans, float* __restrict__ out)
{
    __shared__ unsigned char hist[8][127][20];
    const int w    = threadIdx.x >> 5;
    const int lane = threadIdx.x & 31;
    const int n    = blockIdx.x * 8 + w;       // sequence index 0..1023
    const int j    = lane;
    const bool act = (j < K_);

    float tr[K_];
    #pragma unroll
    for (int i = 0; i < K_; i++) tr[i] = act ? trans[i * K_ + j] : 0.f;

    const float* emn = g_em + (size_t)n * B_ * K_;
    float score = act ? (start[j] + emn[j]) : -1e30f;

    for (int t = 1; t < B_; t++) {
        const float e = act ? emn[t * K_ + j] : 0.f;
        float best = -1e30f; int bi = 0;
        #pragma unroll
        for (int i = 0; i < K_; i++) {
            float si = __shfl_sync(0xffffffffu, score, i);
            float v  = si + tr[i];
            if (v > best) { best = v; bi = i; }   // strict > => first max (jnp.argmax)
        }
        if (act) hist[w][t - 1][j] = (unsigned char)bi;
        score = best + e;
    }

    float v  = act ? (score + endt[j]) : -1e30f;
    int  idx = j;
    #pragma unroll
    for (int off = 16; off; off >>= 1) {
        float ov = __shfl_down_sync(0xffffffffu, v, off);
        int   oi = __shfl_down_sync(0xffffffffu, idx, off);
        if (ov > v || (ov == v && oi < idx)) { v = ov; idx = oi; }
    }
    __syncwarp();  // make hist writes visible to lane 0

    if (lane == 0) {
        int tag = idx;
        float* o = out + (size_t)n * B_;
        o[B_ - 1] = (float)tag;
        for (int t = B_ - 2; t >= 0; t--) {
            tag  = hist[w][t][tag];
            o[t] = (float)tag;
        }
    }
}

// =====================================================================
extern "C" void kernel_launch(void* const* d_in, const int* in_sizes, int n_in,
                              void* d_out, int out_size)
{
    const float* x     = (const float*)d_in[0];
    const float* Wihf  = (const float*)d_in[1];
    const float* Whhf  = (const float*)d_in[2];
    const float* bihf  = (const float*)d_in[3];
    const float* bhhf  = (const float*)d_in[4];
    const float* Wihb  = (const float*)d_in[5];
    const float* Whhb  = (const float*)d_in[6];
    const float* bihb  = (const float*)d_in[7];
    const float* bhhb  = (const float*)d_in[8];
    const float* Wout  = (const float*)d_in[9];
    const float* bout  = (const float*)d_in[10];
    const float* start = (const float*)d_in[11];
    const float* endt  = (const float*)d_in[12];
    const float* trans = (const float*)d_in[13];
    float* out = (float*)d_out;

    cudaFuncSetAttribute(proj_kernel, cudaFuncAttributeMaxDynamicSharedMemorySize, PJ_SMEM);

    proj_kernel<<<(S_ * B_) / PJ_BM, 320, PJ_SMEM>>>(x, Wihf, Wihb, bihf, bhhf, bihb, bhhb);
    // spacers: shift rnn_kernel into the ncu capture slot (4th app launch)
    noop_kernel<<<1, 32>>>();
    noop_kernel<<<1, 32>>>();
    rnn_kernel<<<2 * B_, 128>>>(Whhf, Whhb);
    logits_kernel<<<(S_ * B_) / 256, 256>>>(Wout, bout);
    viterbi_kernel<<<S_ / 8, 256>>>(start, endt, trans, out);
}

// round 4
// speedup vs baseline: 1.3249x; 1.2736x over previous
#include <cuda_runtime.h>
#include <math.h>

#define S_  1024
#define B_  128
#define F_  202
#define H_  100
#define K_  19
#define N2_ 200   // 2*H

// ---- scratch (device globals: no runtime allocation allowed) ----
__device__ float g_xp[(size_t)S_ * B_ * N2_];  // input projections, both dirs
__device__ float g_h [(size_t)S_ * B_ * N2_];  // hidden states [hf | hb]
__device__ float g_em[(size_t)S_ * B_ * K_];   // softmax emissions

// ---- packed dual-fp32 helpers (sm_103a f32x2 pipe) ----
static __device__ __forceinline__ unsigned long long ffma2_(
    unsigned long long a, unsigned long long b, unsigned long long c)
{
    unsigned long long d;
    asm("fma.rn.f32x2 %0, %1, %2, %3;" : "=l"(d) : "l"(a), "l"(b), "l"(c));
    return d;
}
static __device__ __forceinline__ unsigned long long addf2_(
    unsigned long long a, unsigned long long b)
{
    unsigned long long d;
    asm("add.rn.f32x2 %0, %1, %2;" : "=l"(d) : "l"(a), "l"(b));
    return d;
}
static __device__ __forceinline__ float lo_(unsigned long long v) {
    return __uint_as_float((unsigned)(v & 0xffffffffull));
}
static __device__ __forceinline__ float hi_(unsigned long long v) {
    return __uint_as_float((unsigned)(v >> 32));
}
static __device__ __forceinline__ unsigned long long pack2_(float lo, float hi) {
    unsigned long long r;
    asm("mov.b64 %0, {%1, %2};" : "=l"(r) : "f"(lo), "f"(hi));
    return r;
}
// predicated stores (single @p instruction, no BSSY/BSYNC envelope)
static __device__ __forceinline__ void sts_pred_(int pred, unsigned addr, float v) {
    asm volatile("{ .reg .pred p; setp.ne.s32 p, %0, 0; @p st.shared.f32 [%1], %2; }"
                 :: "r"(pred), "r"(addr), "f"(v));
}
static __device__ __forceinline__ void stg_pred_(int pred, float* ptr, float v) {
    asm volatile("{ .reg .pred p; setp.ne.s32 p, %0, 0; @p st.global.f32 [%1], %2; }"
                 :: "r"(pred), "l"(ptr), "f"(v));
}
static __device__ __forceinline__ unsigned smem_u32_(const void* p) {
    unsigned a;
    asm("{ .reg .u64 t; cvta.to.shared.u64 t, %1; cvt.u32.u64 %0, t; }" : "=r"(a) : "l"(p));
    return a;
}

// profiling-slot spacer (ncu captures the 4th app launch; make it proj)
__global__ void noop_kernel() {}

// =====================================================================
// Kernel 1: input projection  xp = x @ W_ih^T + b_ih + b_hh  (both dirs)
//   Epilogue staged through SMEM -> coalesced global stores.
// =====================================================================
#define PJ_BM   64
#define PJ_FP   204              // F padded to multiple of 4 (zero-filled)
#define PJ_AS4  53               // A row stride (16B units) -> 212 floats
#define PJ_BS4  51               // B row stride (16B units) -> 204 floats
#define PJ_A_F4 (PJ_BM * PJ_AS4) // 3392
#define PJ_B_F4 (N2_ * PJ_BS4)   // 10200
#define PJ_SMEM ((PJ_A_F4 + PJ_B_F4) * 16)  // 217472 bytes
#define PJ_OS   209              // staged output row stride (floats), odd -> no bank conflicts

__global__ __launch_bounds__(320, 1) void proj_kernel(
    const float* __restrict__ x,
    const float* __restrict__ Wf, const float* __restrict__ Wb,
    const float* __restrict__ bihf, const float* __restrict__ bhhf,
    const float* __restrict__ bihb, const float* __restrict__ bhhb)
{
    extern __shared__ ulonglong2 sm2[];
    float* Ash = (float*)sm2;                  // [64][212]
    float* Bsh = (float*)(sm2 + PJ_A_F4);      // [200][204]
    const int tid = threadIdx.x;
    const int m0  = blockIdx.x * PJ_BM;

    for (int e = tid; e < PJ_BM * PJ_FP; e += 320) {
        int r = e / PJ_FP, f = e - r * PJ_FP;
        Ash[r * (PJ_AS4 * 4) + f] = (f < F_) ? x[(size_t)(m0 + r) * F_ + f] : 0.f;
    }
    for (int e = tid; e < N2_ * PJ_FP; e += 320) {
        int n = e / PJ_FP, f = e - n * PJ_FP;
        float v = 0.f;
        if (f < F_) v = (n < H_) ? Wf[n * F_ + f] : Wb[(n - H_) * F_ + f];
        Bsh[n * PJ_FP + f] = v;
    }
    __syncthreads();

    const int tx = tid & 15;    // row group (strided rows)
    const int ty = tid >> 4;    // col group 0..19
    const ulonglong2* A2 = sm2;
    const ulonglong2* B2 = sm2 + PJ_A_F4;

    unsigned long long acc2[4][10];
    #pragma unroll
    for (int i = 0; i < 4; i++)
        #pragma unroll
        for (int j = 0; j < 10; j++) acc2[i][j] = 0ull;

    for (int kk = 0; kk < 51; kk++) {
        ulonglong2 a[4], b[10];
        #pragma unroll
        for (int i = 0; i < 4; i++) a[i] = A2[(tx + 16 * i) * PJ_AS4 + kk];
        #pragma unroll
        for (int j = 0; j < 10; j++) b[j] = B2[(ty + 20 * j) * PJ_BS4 + kk];
        #pragma unroll
        for (int i = 0; i < 4; i++)
            #pragma unroll
            for (int j = 0; j < 10; j++) {
                acc2[i][j] = ffma2_(a[i].x, b[j].x, acc2[i][j]);
                acc2[i][j] = ffma2_(a[i].y, b[j].y, acc2[i][j]);
            }
    }

    // stage outputs to SMEM (conflict-free odd stride), then coalesced store
    __syncthreads();
    float* staged = (float*)sm2;   // [64][209]
    #pragma unroll
    for (int j = 0; j < 10; j++) {
        int n = ty + 20 * j;
        float bias = (n < H_) ? (bihf[n] + bhhf[n]) : (bihb[n - H_] + bhhb[n - H_]);
        #pragma unroll
        for (int i = 0; i < 4; i++)
            staged[(tx + 16 * i) * PJ_OS + n] = lo_(acc2[i][j]) + hi_(acc2[i][j]) + bias;
    }
    __syncthreads();
    float* gout = g_xp + (size_t)m0 * N2_;
    for (int e = tid; e < PJ_BM * N2_; e += 320) {
        int r = e / N2_, c = e - r * N2_;
        gout[e] = staged[r * PJ_OS + c];
    }
}

// =====================================================================
// Kernel 2: recurrent scans. One CTA (128 thr) per (direction,batch) chain.
//   Fully uniform (no divergence envelopes): padded to 104, clamped addrs,
//   predicated stores. 8 rotating packed accumulators -> chain depth ~7.
// =====================================================================
__global__ __launch_bounds__(128) void rnn_kernel(
    const float* __restrict__ Whhf, const float* __restrict__ Whhb)
{
    const int chain = blockIdx.x;        // 0..255
    const int dir   = chain >> 7;        // 0 fwd, 1 bwd
    const int b     = chain & 127;
    const int j     = threadIdx.x;       // 0..127
    const int jc    = (j < H_) ? j : (H_ - 1);  // clamped lane
    const int act   = (j < H_) ? 1 : 0;

    __shared__ __align__(16) float hs[2][104];

    const float* Whh = dir ? Whhb : Whhf;
    unsigned long long w2[52];           // 104 weights packed (last 4 zero)
    {
        const ulonglong2* wp = (const ulonglong2*)(Whh + jc * H_);
        #pragma unroll
        for (int k = 0; k < 25; k++) { ulonglong2 t = wp[k]; w2[2*k] = t.x; w2[2*k+1] = t.y; }
        w2[50] = 0ull; w2[51] = 0ull;
    }
    if (j < 104) { hs[0][j] = 0.f; hs[1][j] = 0.f; }

    // desync co-resident CTAs so their stall phases interleave
    if (chain & 1) __nanosleep(150);
    __syncthreads();

    const unsigned hs_base = smem_u32_(&hs[0][0]);
    const float* xpb = g_xp + (size_t)b * N2_ + dir * H_ + jc;
    float*       hgb = g_h  + (size_t)b * N2_ + dir * H_ + jc;
    const int s0 = dir ? (S_ - 1) : 0;
    const int ds = dir ? -1 : 1;
    const int STRIDE = B_ * N2_;  // 25600

    float xq[4];
    #pragma unroll
    for (int q = 0; q < 4; q++) xq[q] = xpb[(size_t)(s0 + ds * q) * STRIDE];

    int p = 0;
    #pragma unroll 4
    for (int t = 0; t < S_; t++) {
        const int s = s0 + ds * t;
        const float x0 = xq[t & 3];
        int tp = t + 4; tp = (tp < S_) ? tp : (S_ - 1);     // clamp, branch-free
        xq[t & 3] = xpb[(size_t)(s0 + ds * tp) * STRIDE];

        unsigned long long a[8];
        a[0] = pack2_(x0, 0.f);
        #pragma unroll
        for (int q = 1; q < 8; q++) a[q] = 0ull;

        const ulonglong2* hv2 = (const ulonglong2*)hs[p];
        #pragma unroll
        for (int k = 0; k < 26; k++) {
            ulonglong2 h2 = hv2[k];
            a[(2*k)     & 7] = ffma2_(w2[2*k],     h2.x, a[(2*k)     & 7]);
            a[(2*k + 1) & 7] = ffma2_(w2[2*k + 1], h2.y, a[(2*k + 1) & 7]);
        }
        unsigned long long r0 = addf2_(addf2_(a[0], a[4]), addf2_(a[1], a[5]));
        unsigned long long r1 = addf2_(addf2_(a[2], a[6]), addf2_(a[3], a[7]));
        unsigned long long rr = addf2_(r0, r1);
        float acc = lo_(rr) + hi_(rr);

        // tanh(x) = 1 - 2/(e^{2x}+1); inf-safe, ~1e-7 abs err
        float e2 = __expf(acc + acc);
        float hn = 1.f - __fdividef(2.f, e2 + 1.f);

        sts_pred_(act, hs_base + (unsigned)((p ^ 1) * 104 + j) * 4u, hn);
        stg_pred_(act, hgb + (size_t)s * STRIDE, hn);
        __syncthreads();
        p ^= 1;
    }
}

// =====================================================================
// Kernel 3: logits + softmax -> emissions. Thread per (s,b) row.
// =====================================================================
__global__ __launch_bounds__(256) void logits_kernel(
    const float* __restrict__ Wout, const float* __restrict__ bout)
{
    __shared__ __align__(16) float wt[N2_ * 20];   // W_out^T, K padded 19->20
    const int tid = threadIdx.x;
    for (int e = tid; e < N2_ * 20; e += 256) {
        int f = e / 20, k = e - f * 20;
        wt[e] = (k < K_) ? Wout[k * N2_ + f] : 0.f;
    }
    __syncthreads();

    const int m = blockIdx.x * 256 + tid;     // row index, always < 131072
    const float4* hp = (const float4*)(g_h + (size_t)m * N2_);
    const ulonglong2* wt2 = (const ulonglong2*)wt;   // [f][5] of (k-pair, k-pair)

    unsigned long long acc2[10];
    #pragma unroll
    for (int q = 0; q < 10; q++) acc2[q] = 0ull;

    for (int f4 = 0; f4 < 50; f4++) {
        float4 hv = __ldg(&hp[f4]);
        float hh[4] = {hv.x, hv.y, hv.z, hv.w};
        #pragma unroll
        for (int c = 0; c < 4; c++) {
            const int f = f4 * 4 + c;
            const unsigned long long hb = pack2_(hh[c], hh[c]);
            #pragma unroll
            for (int q = 0; q < 5; q++) {
                ulonglong2 wv = wt2[f * 5 + q];
                acc2[2*q]     = ffma2_(hb, wv.x, acc2[2*q]);
                acc2[2*q + 1] = ffma2_(hb, wv.y, acc2[2*q + 1]);
            }
        }
    }

    float acc[20];
    #pragma unroll
    for (int q = 0; q < 10; q++) { acc[2*q] = lo_(acc2[q]); acc[2*q+1] = hi_(acc2[q]); }

    float mx = -1e30f;
    #pragma unroll
    for (int k = 0; k < K_; k++) { acc[k] += __ldg(&bout[k]); mx = fmaxf(mx, acc[k]); }
    float sum = 0.f;
    #pragma unroll
    for (int k = 0; k < K_; k++) { acc[k] = __expf(acc[k] - mx); sum += acc[k]; }
    const float inv = 1.f / sum;
    float* e = g_em + (size_t)m * K_;
    #pragma unroll
    for (int k = 0; k < K_; k++) e[k] = acc[k] * inv;
}

// =====================================================================
// Kernel 4: Viterbi decode. Warp per sequence (n = s index, T = B steps).
// =====================================================================
__global__ __launch_bounds__(256) void viterbi_kernel(
    const float* __restrict__ start, const float* __restrict__ endt,
    const float* __restrict__ trans, float* __restrict__ out)
{
    __shared__ unsigned char hist[8][127][20];
    const int w    = threadIdx.x >> 5;
    const int lane = threadIdx.x & 31;
    const int n    = blockIdx.x * 8 + w;       // sequence index 0..1023
    const int j    = lane;
    const bool act = (j < K_);

    float tr[K_];
    #pragma unroll
    for (int i = 0; i < K_; i++) tr[i] = act ? trans[i * K_ + j] : 0.f;

    const float* emn = g_em + (size_t)n * B_ * K_;
    float score = act ? (start[j] + emn[j]) : -1e30f;

    for (int t = 1; t < B_; t++) {
        const float e = act ? emn[t * K_ + j] : 0.f;
        float best = -1e30f; int bi = 0;
        #pragma unroll
        for (int i = 0; i < K_; i++) {
            float si = __shfl_sync(0xffffffffu, score, i);
            float v  = si + tr[i];
            if (v > best) { best = v; bi = i; }   // strict > => first max (jnp.argmax)
        }
        if (act) hist[w][t - 1][j] = (unsigned char)bi;
        score = best + e;
    }

    float v  = act ? (score + endt[j]) : -1e30f;
    int  idx = j;
    #pragma unroll
    for (int off = 16; off; off >>= 1) {
        float ov = __shfl_down_sync(0xffffffffu, v, off);
        int   oi = __shfl_down_sync(0xffffffffu, idx, off);
        if (ov > v || (ov == v && oi < idx)) { v = ov; idx = oi; }
    }
    __syncwarp();  // make hist writes visible to lane 0

    if (lane == 0) {
        int tag = idx;
        float* o = out + (size_t)n * B_;
        o[B_ - 1] = (float)tag;
        for (int t = B_ - 2; t >= 0; t--) {
            tag  = hist[w][t][tag];
            o[t] = (float)tag;
        }
    }
}

// =====================================================================
extern "C" void kernel_launch(void* const* d_in, const int* in_sizes, int n_in,
                              void* d_out, int out_size)
{
    const float* x     = (const float*)d_in[0];
    const float* Wihf  = (const float*)d_in[1];
    const float* Whhf  = (const float*)d_in[2];
    const float* bihf  = (const float*)d_in[3];
    const float* bhhf  = (const float*)d_in[4];
    const float* Wihb  = (const float*)d_in[5];
    const float* Whhb  = (const float*)d_in[6];
    const float* bihb  = (const float*)d_in[7];
    const float* bhhb  = (const float*)d_in[8];
    const float* Wout  = (const float*)d_in[9];
    const float* bout  = (const float*)d_in[10];
    const float* start = (const float*)d_in[11];
    const float* endt  = (const float*)d_in[12];
    const float* trans = (const float*)d_in[13];
    float* out = (float*)d_out;

    cudaFuncSetAttribute(proj_kernel, cudaFuncAttributeMaxDynamicSharedMemorySize, PJ_SMEM);

    // spacers: shift proj_kernel into the ncu capture slot (4th app launch)
    noop_kernel<<<1, 32>>>();
    noop_kernel<<<1, 32>>>();
    noop_kernel<<<1, 32>>>();
    proj_kernel<<<(S_ * B_) / PJ_BM, 320, PJ_SMEM>>>(x, Wihf, Wihb, bihf, bhhf, bihb, bhhb);
    rnn_kernel<<<2 * B_, 128>>>(Whhf, Whhb);
    logits_kernel<<<(S_ * B_) / 256, 256>>>(Wout, bout);
    viterbi_kernel<<<S_ / 8, 256>>>(start, endt, trans, out);
}

// round 5
// speedup vs baseline: 1.6181x; 1.2213x over previous
#include <cuda_runtime.h>
#include <math.h>

#define S_  1024
#define B_  128
#define F_  202
#define H_  100
#define K_  19
#define N2_ 200   // 2*H

// ---- scratch (device globals: no runtime allocation allowed) ----
__device__ float g_xp[(size_t)S_ * B_ * N2_];  // input projections, both dirs
__device__ float g_h [(size_t)S_ * B_ * N2_];  // hidden states [hf | hb]
__device__ float g_em[(size_t)S_ * B_ * K_];   // softmax emissions

// ---- packed dual-fp32 helpers (sm_103a f32x2 pipe) ----
static __device__ __forceinline__ unsigned long long ffma2_(
    unsigned long long a, unsigned long long b, unsigned long long c)
{
    unsigned long long d;
    asm("fma.rn.f32x2 %0, %1, %2, %3;" : "=l"(d) : "l"(a), "l"(b), "l"(c));
    return d;
}
static __device__ __forceinline__ unsigned long long addf2_(
    unsigned long long a, unsigned long long b)
{
    unsigned long long d;
    asm("add.rn.f32x2 %0, %1, %2;" : "=l"(d) : "l"(a), "l"(b));
    return d;
}
static __device__ __forceinline__ float lo_(unsigned long long v) {
    return __uint_as_float((unsigned)(v & 0xffffffffull));
}
static __device__ __forceinline__ float hi_(unsigned long long v) {
    return __uint_as_float((unsigned)(v >> 32));
}
static __device__ __forceinline__ unsigned long long pack2_(float lo, float hi) {
    unsigned long long r;
    asm("mov.b64 %0, {%1, %2};" : "=l"(r) : "f"(lo), "f"(hi));
    return r;
}
// predicated stores (single @p instruction, no BSSY/BSYNC envelope)
static __device__ __forceinline__ void sts_pred_(int pred, unsigned addr, float v) {
    asm volatile("{ .reg .pred p; setp.ne.s32 p, %0, 0; @p st.shared.f32 [%1], %2; }"
                 :: "r"(pred), "r"(addr), "f"(v));
}
static __device__ __forceinline__ void stg_pred_(int pred, float* ptr, float v) {
    asm volatile("{ .reg .pred p; setp.ne.s32 p, %0, 0; @p st.global.f32 [%1], %2; }"
                 :: "r"(pred), "l"(ptr), "f"(v));
}
static __device__ __forceinline__ unsigned smem_u32_(const void* p) {
    unsigned a;
    asm("{ .reg .u64 t; cvta.to.shared.u64 t, %1; cvt.u32.u64 %0, t; }" : "=r"(a) : "l"(p));
    return a;
}

// profiling-slot spacer (ncu captures the 4th app launch; keep it proj)
__global__ void noop_kernel() {}

// =====================================================================
// Kernel 1: input projection  xp = x @ W_ih^T + b_ih + b_hh  (both dirs)
//   64x200 tile, full K in SMEM. 640 threads, 4x5 micro-tile:
//   regs ~95/thread -> 20 warps/SM (5/SMSP) for latency hiding.
// =====================================================================
#define PJ_BM   64
#define PJ_FP   204              // F padded to multiple of 4 (zero-filled)
#define PJ_AS4  53               // A row stride (16B units) -> 212 floats
#define PJ_BS4  51               // B row stride (16B units) -> 204 floats
#define PJ_A_F4 (PJ_BM * PJ_AS4) // 3392
#define PJ_B_F4 (N2_ * PJ_BS4)   // 10200
#define PJ_SMEM ((PJ_A_F4 + PJ_B_F4) * 16)  // 217472 bytes
#define PJ_OS   209              // staged output row stride (floats)
#define PJ_T    640

__global__ __launch_bounds__(PJ_T, 1) void proj_kernel(
    const float* __restrict__ x,
    const float* __restrict__ Wf, const float* __restrict__ Wb,
    const float* __restrict__ bihf, const float* __restrict__ bhhf,
    const float* __restrict__ bihb, const float* __restrict__ bhhb)
{
    extern __shared__ ulonglong2 sm2[];
    float* Ash = (float*)sm2;                  // [64][212]
    float* Bsh = (float*)(sm2 + PJ_A_F4);      // [200][204]
    const int tid = threadIdx.x;
    const int m0  = blockIdx.x * PJ_BM;

    for (int e = tid; e < PJ_BM * PJ_FP; e += PJ_T) {
        int r = e / PJ_FP, f = e - r * PJ_FP;
        Ash[r * (PJ_AS4 * 4) + f] = (f < F_) ? x[(size_t)(m0 + r) * F_ + f] : 0.f;
    }
    for (int e = tid; e < N2_ * PJ_FP; e += PJ_T) {
        int n = e / PJ_FP, f = e - n * PJ_FP;
        float v = 0.f;
        if (f < F_) v = (n < H_) ? Wf[n * F_ + f] : Wb[(n - H_) * F_ + f];
        Bsh[n * PJ_FP + f] = v;
    }
    __syncthreads();

    const int tx = tid & 15;    // row group: rows tx + 16*i, i=0..3
    const int ty = tid >> 4;    // col group 0..39: cols ty + 40*j, j=0..4
    const ulonglong2* A2 = sm2;
    const ulonglong2* B2 = sm2 + PJ_A_F4;

    unsigned long long acc2[4][5];
    #pragma unroll
    for (int i = 0; i < 4; i++)
        #pragma unroll
        for (int j = 0; j < 5; j++) acc2[i][j] = 0ull;

    for (int kk = 0; kk < 51; kk++) {
        ulonglong2 a[4], b[5];
        #pragma unroll
        for (int i = 0; i < 4; i++) a[i] = A2[(tx + 16 * i) * PJ_AS4 + kk];
        #pragma unroll
        for (int j = 0; j < 5; j++) b[j] = B2[(ty + 40 * j) * PJ_BS4 + kk];
        #pragma unroll
        for (int i = 0; i < 4; i++)
            #pragma unroll
            for (int j = 0; j < 5; j++) {
                acc2[i][j] = ffma2_(a[i].x, b[j].x, acc2[i][j]);
                acc2[i][j] = ffma2_(a[i].y, b[j].y, acc2[i][j]);
            }
    }

    // stage outputs to SMEM (conflict-free odd stride), then coalesced store
    __syncthreads();
    float* staged = (float*)sm2;   // [64][209]
    #pragma unroll
    for (int j = 0; j < 5; j++) {
        int n = ty + 40 * j;
        float bias = (n < H_) ? (bihf[n] + bhhf[n]) : (bihb[n - H_] + bhhb[n - H_]);
        #pragma unroll
        for (int i = 0; i < 4; i++)
            staged[(tx + 16 * i) * PJ_OS + n] = lo_(acc2[i][j]) + hi_(acc2[i][j]) + bias;
    }
    __syncthreads();
    float* gout = g_xp + (size_t)m0 * N2_;
    for (int e = tid; e < PJ_BM * N2_; e += PJ_T) {
        int r = e / N2_, c = e - r * N2_;
        gout[e] = staged[r * PJ_OS + c];
    }
}

// =====================================================================
// Kernel 2: recurrent scans. One CTA (128 thr) per (direction,batch) chain.
// =====================================================================
__global__ __launch_bounds__(128) void rnn_kernel(
    const float* __restrict__ Whhf, const float* __restrict__ Whhb)
{
    const int chain = blockIdx.x;        // 0..255
    const int dir   = chain >> 7;        // 0 fwd, 1 bwd
    const int b     = chain & 127;
    const int j     = threadIdx.x;       // 0..127
    const int jc    = (j < H_) ? j : (H_ - 1);  // clamped lane
    const int act   = (j < H_) ? 1 : 0;

    __shared__ __align__(16) float hs[2][104];

    const float* Whh = dir ? Whhb : Whhf;
    unsigned long long w2[52];           // 104 weights packed (last 4 zero)
    {
        const ulonglong2* wp = (const ulonglong2*)(Whh + jc * H_);
        #pragma unroll
        for (int k = 0; k < 25; k++) { ulonglong2 t = wp[k]; w2[2*k] = t.x; w2[2*k+1] = t.y; }
        w2[50] = 0ull; w2[51] = 0ull;
    }
    if (j < 104) { hs[0][j] = 0.f; hs[1][j] = 0.f; }

    // desync co-resident CTAs so their stall phases interleave
    if (chain & 1) __nanosleep(150);
    __syncthreads();

    const unsigned hs_base = smem_u32_(&hs[0][0]);
    const float* xpb = g_xp + (size_t)b * N2_ + dir * H_ + jc;
    float*       hgb = g_h  + (size_t)b * N2_ + dir * H_ + jc;
    const int s0 = dir ? (S_ - 1) : 0;
    const int ds = dir ? -1 : 1;
    const int STRIDE = B_ * N2_;  // 25600

    float xq[4];
    #pragma unroll
    for (int q = 0; q < 4; q++) xq[q] = xpb[(size_t)(s0 + ds * q) * STRIDE];

    int p = 0;
    #pragma unroll 4
    for (int t = 0; t < S_; t++) {
        const int s = s0 + ds * t;
        const float x0 = xq[t & 3];
        int tp = t + 4; tp = (tp < S_) ? tp : (S_ - 1);     // clamp, branch-free
        xq[t & 3] = xpb[(size_t)(s0 + ds * tp) * STRIDE];

        unsigned long long a[8];
        a[0] = pack2_(x0, 0.f);
        #pragma unroll
        for (int q = 1; q < 8; q++) a[q] = 0ull;

        const ulonglong2* hv2 = (const ulonglong2*)hs[p];
        #pragma unroll
        for (int k = 0; k < 26; k++) {
            ulonglong2 h2 = hv2[k];
            a[(2*k)     & 7] = ffma2_(w2[2*k],     h2.x, a[(2*k)     & 7]);
            a[(2*k + 1) & 7] = ffma2_(w2[2*k + 1], h2.y, a[(2*k + 1) & 7]);
        }
        unsigned long long r0 = addf2_(addf2_(a[0], a[4]), addf2_(a[1], a[5]));
        unsigned long long r1 = addf2_(addf2_(a[2], a[6]), addf2_(a[3], a[7]));
        unsigned long long rr = addf2_(r0, r1);
        float acc = lo_(rr) + hi_(rr);

        // tanh(x) = 1 - 2/(e^{2x}+1); inf-safe, ~1e-7 abs err
        float e2 = __expf(acc + acc);
        float hn = 1.f - __fdividef(2.f, e2 + 1.f);

        sts_pred_(act, hs_base + (unsigned)((p ^ 1) * 104 + j) * 4u, hn);
        stg_pred_(act, hgb + (size_t)s * STRIDE, hn);
        __syncthreads();
        p ^= 1;
    }
}

// =====================================================================
// Kernel 3: logits + softmax -> emissions. Thread per (s,b) row.
// =====================================================================
__global__ __launch_bounds__(256) void logits_kernel(
    const float* __restrict__ Wout, const float* __restrict__ bout)
{
    __shared__ __align__(16) float wt[N2_ * 20];   // W_out^T, K padded 19->20
    const int tid = threadIdx.x;
    for (int e = tid; e < N2_ * 20; e += 256) {
        int f = e / 20, k = e - f * 20;
        wt[e] = (k < K_) ? Wout[k * N2_ + f] : 0.f;
    }
    __syncthreads();

    const int m = blockIdx.x * 256 + tid;     // row index, always < 131072
    const float4* hp = (const float4*)(g_h + (size_t)m * N2_);
    const ulonglong2* wt2 = (const ulonglong2*)wt;   // [f][5] of (k-pair, k-pair)

    unsigned long long acc2[10];
    #pragma unroll
    for (int q = 0; q < 10; q++) acc2[q] = 0ull;

    for (int f4 = 0; f4 < 50; f4++) {
        float4 hv = __ldg(&hp[f4]);
        float hh[4] = {hv.x, hv.y, hv.z, hv.w};
        #pragma unroll
        for (int c = 0; c < 4; c++) {
            const int f = f4 * 4 + c;
            const unsigned long long hb = pack2_(hh[c], hh[c]);
            #pragma unroll
            for (int q = 0; q < 5; q++) {
                ulonglong2 wv = wt2[f * 5 + q];
                acc2[2*q]     = ffma2_(hb, wv.x, acc2[2*q]);
                acc2[2*q + 1] = ffma2_(hb, wv.y, acc2[2*q + 1]);
            }
        }
    }

    float acc[20];
    #pragma unroll
    for (int q = 0; q < 10; q++) { acc[2*q] = lo_(acc2[q]); acc[2*q+1] = hi_(acc2[q]); }

    float mx = -1e30f;
    #pragma unroll
    for (int k = 0; k < K_; k++) { acc[k] += __ldg(&bout[k]); mx = fmaxf(mx, acc[k]); }
    float sum = 0.f;
    #pragma unroll
    for (int k = 0; k < K_; k++) { acc[k] = __expf(acc[k] - mx); sum += acc[k]; }
    const float inv = 1.f / sum;
    float* e = g_em + (size_t)m * K_;
    #pragma unroll
    for (int k = 0; k < K_; k++) e[k] = acc[k] * inv;
}

// =====================================================================
// Kernel 4: Viterbi decode. Warp per sequence (n = s index, T = B steps).
// =====================================================================
__global__ __launch_bounds__(256) void viterbi_kernel(
    const float* __restrict__ start, const float* __restrict__ endt,
    const float* __restrict__ trans, float* __restrict__ out)
{
    __shared__ unsigned char hist[8][127][20];
    const int w    = threadIdx.x >> 5;
    const int lane = threadIdx.x & 31;
    const int n    = blockIdx.x * 8 + w;       // sequence index 0..1023
    const int j    = lane;
    const bool act = (j < K_);

    float tr[K_];
    #pragma unroll
    for (int i = 0; i < K_; i++) tr[i] = act ? trans[i * K_ + j] : 0.f;

    const float* emn = g_em + (size_t)n * B_ * K_;
    float score = act ? (start[j] + emn[j]) : -1e30f;

    for (int t = 1; t < B_; t++) {
        const float e = act ? emn[t * K_ + j] : 0.f;
        float best = -1e30f; int bi = 0;
        #pragma unroll
        for (int i = 0; i < K_; i++) {
            float si = __shfl_sync(0xffffffffu, score, i);
            float v  = si + tr[i];
            if (v > best) { best = v; bi = i; }   // strict > => first max (jnp.argmax)
        }
        if (act) hist[w][t - 1][j] = (unsigned char)bi;
        score = best + e;
    }

    float v  = act ? (score + endt[j]) : -1e30f;
    int  idx = j;
    #pragma unroll
    for (int off = 16; off; off >>= 1) {
        float ov = __shfl_down_sync(0xffffffffu, v, off);
        int   oi = __shfl_down_sync(0xffffffffu, idx, off);
        if (ov > v || (ov == v && oi < idx)) { v = ov; idx = oi; }
    }
    __syncwarp();  // make hist writes visible to lane 0

    if (lane == 0) {
        int tag = idx;
        float* o = out + (size_t)n * B_;
        o[B_ - 1] = (float)tag;
        for (int t = B_ - 2; t >= 0; t--) {
            tag  = hist[w][t][tag];
            o[t] = (float)tag;
        }
    }
}

// =====================================================================
extern "C" void kernel_launch(void* const* d_in, const int* in_sizes, int n_in,
                              void* d_out, int out_size)
{
    const float* x     = (const float*)d_in[0];
    const float* Wihf  = (const float*)d_in[1];
    const float* Whhf  = (const float*)d_in[2];
    const float* bihf  = (const float*)d_in[3];
    const float* bhhf  = (const float*)d_in[4];
    const float* Wihb  = (const float*)d_in[5];
    const float* Whhb  = (const float*)d_in[6];
    const float* bihb  = (const float*)d_in[7];
    const float* bhhb  = (const float*)d_in[8];
    const float* Wout  = (const float*)d_in[9];
    const float* bout  = (const float*)d_in[10];
    const float* start = (const float*)d_in[11];
    const float* endt  = (const float*)d_in[12];
    const float* trans = (const float*)d_in[13];
    float* out = (float*)d_out;

    cudaFuncSetAttribute(proj_kernel, cudaFuncAttributeMaxDynamicSharedMemorySize, PJ_SMEM);

    // spacers: keep proj_kernel in the ncu capture slot (4th app launch)
    noop_kernel<<<1, 32>>>();
    noop_kernel<<<1, 32>>>();
    noop_kernel<<<1, 32>>>();
    proj_kernel<<<(S_ * B_) / PJ_BM, PJ_T, PJ_SMEM>>>(x, Wihf, Wihb, bihf, bhhf, bihb, bhhb);
    rnn_kernel<<<2 * B_, 128>>>(Whhf, Whhb);
    logits_kernel<<<(S_ * B_) / 256, 256>>>(Wout, bout);
    viterbi_kernel<<<S_ / 8, 256>>>(start, endt, trans, out);
}

// round 6
// speedup vs baseline: 1.7024x; 1.0521x over previous
#include <cuda_runtime.h>
#include <math.h>

#define S_  1024
#define B_  128
#define F_  202
#define H_  100
#define K_  19
#define N2_ 200   // 2*H

// ---- scratch (device globals: no runtime allocation allowed) ----
__device__ float g_xp[(size_t)S_ * B_ * N2_];  // input projections, both dirs
__device__ float g_h [(size_t)S_ * B_ * N2_];  // hidden states [hf | hb]
__device__ float g_em[(size_t)S_ * B_ * K_];   // softmax emissions

// ---- packed dual-fp32 helpers (sm_103a f32x2 pipe) ----
static __device__ __forceinline__ unsigned long long ffma2_(
    unsigned long long a, unsigned long long b, unsigned long long c)
{
    unsigned long long d;
    asm("fma.rn.f32x2 %0, %1, %2, %3;" : "=l"(d) : "l"(a), "l"(b), "l"(c));
    return d;
}
static __device__ __forceinline__ unsigned long long addf2_(
    unsigned long long a, unsigned long long b)
{
    unsigned long long d;
    asm("add.rn.f32x2 %0, %1, %2;" : "=l"(d) : "l"(a), "l"(b));
    return d;
}
static __device__ __forceinline__ float lo_(unsigned long long v) {
    return __uint_as_float((unsigned)(v & 0xffffffffull));
}
static __device__ __forceinline__ float hi_(unsigned long long v) {
    return __uint_as_float((unsigned)(v >> 32));
}
static __device__ __forceinline__ unsigned long long pack2_(float lo, float hi) {
    unsigned long long r;
    asm("mov.b64 %0, {%1, %2};" : "=l"(r) : "f"(lo), "f"(hi));
    return r;
}
// predicated stores (single @p instruction, no BSSY/BSYNC envelope)
static __device__ __forceinline__ void sts_pred_(int pred, unsigned addr, float v) {
    asm volatile("{ .reg .pred p; setp.ne.s32 p, %0, 0; @p st.shared.f32 [%1], %2; }"
                 :: "r"(pred), "r"(addr), "f"(v));
}
static __device__ __forceinline__ void stg_pred_(int pred, float* ptr, float v) {
    asm volatile("{ .reg .pred p; setp.ne.s32 p, %0, 0; @p st.global.f32 [%1], %2; }"
                 :: "r"(pred), "l"(ptr), "f"(v));
}
static __device__ __forceinline__ unsigned smem_u32_(const void* p) {
    unsigned a;
    asm("{ .reg .u64 t; cvta.to.shared.u64 t, %1; cvt.u32.u64 %0, t; }" : "=r"(a) : "l"(p));
    return a;
}

// profiling-slot spacer (ncu captures the 4th app launch; keep it proj)
__global__ void noop_kernel() {}

// =====================================================================
// Kernel 1: input projection  xp = x @ W_ih^T + b_ih + b_hh  (both dirs)
//   64x200 tile, full K in SMEM, 640 threads.
//   Warp mapping: lane = A-row (32 distinct rows, no duplication,
//   conflict-free LDS.128); warp id = B-col group (fully uniform
//   broadcast B loads). Micro-tile 2x10 per thread.
// =====================================================================
#define PJ_BM   64
#define PJ_FP   204              // F padded to multiple of 4 (zero-filled)
#define PJ_AS4  53               // A row stride (16B units) -> 212 floats
#define PJ_BS4  51               // B row stride (16B units) -> 204 floats
#define PJ_A_F4 (PJ_BM * PJ_AS4) // 3392
#define PJ_B_F4 (N2_ * PJ_BS4)   // 10200
#define PJ_SMEM ((PJ_A_F4 + PJ_B_F4) * 16)  // 217472 bytes
#define PJ_OS   209              // staged output row stride (floats)
#define PJ_T    640

__global__ __launch_bounds__(PJ_T, 1) void proj_kernel(
    const float* __restrict__ x,
    const float* __restrict__ Wf, const float* __restrict__ Wb,
    const float* __restrict__ bihf, const float* __restrict__ bhhf,
    const float* __restrict__ bihb, const float* __restrict__ bhhb)
{
    extern __shared__ ulonglong2 sm2[];
    float* Ash = (float*)sm2;                  // [64][212]
    float* Bsh = (float*)(sm2 + PJ_A_F4);      // [200][204]
    const int tid = threadIdx.x;
    const int m0  = blockIdx.x * PJ_BM;

    for (int e = tid; e < PJ_BM * PJ_FP; e += PJ_T) {
        int r = e / PJ_FP, f = e - r * PJ_FP;
        Ash[r * (PJ_AS4 * 4) + f] = (f < F_) ? x[(size_t)(m0 + r) * F_ + f] : 0.f;
    }
    for (int e = tid; e < N2_ * PJ_FP; e += PJ_T) {
        int n = e / PJ_FP, f = e - n * PJ_FP;
        float v = 0.f;
        if (f < F_) v = (n < H_) ? Wf[n * F_ + f] : Wb[(n - H_) * F_ + f];
        Bsh[n * PJ_FP + f] = v;
    }
    __syncthreads();

    const int tx = tid & 31;    // A rows: tx, tx+32 (32 distinct lanes/warp)
    const int ty = tid >> 5;    // warp id 0..19 -> B cols ty + 20*j (uniform)
    const ulonglong2* A2 = sm2;
    const ulonglong2* B2 = sm2 + PJ_A_F4;

    unsigned long long acc2[2][10];
    #pragma unroll
    for (int i = 0; i < 2; i++)
        #pragma unroll
        for (int j = 0; j < 10; j++) acc2[i][j] = 0ull;

    #pragma unroll 3
    for (int kk = 0; kk < 51; kk++) {
        ulonglong2 a0 = A2[tx * PJ_AS4 + kk];
        ulonglong2 a1 = A2[(tx + 32) * PJ_AS4 + kk];
        #pragma unroll
        for (int jh = 0; jh < 2; jh++) {
            ulonglong2 b[5];
            #pragma unroll
            for (int j = 0; j < 5; j++)
                b[j] = B2[(ty + 20 * (jh * 5 + j)) * PJ_BS4 + kk];
            #pragma unroll
            for (int j = 0; j < 5; j++) {
                const int jj = jh * 5 + j;
                acc2[0][jj] = ffma2_(a0.x, b[j].x, acc2[0][jj]);
                acc2[0][jj] = ffma2_(a0.y, b[j].y, acc2[0][jj]);
                acc2[1][jj] = ffma2_(a1.x, b[j].x, acc2[1][jj]);
                acc2[1][jj] = ffma2_(a1.y, b[j].y, acc2[1][jj]);
            }
        }
    }

    // stage outputs to SMEM (conflict-free odd stride), then coalesced store
    __syncthreads();
    float* staged = (float*)sm2;   // [64][209]
    #pragma unroll
    for (int j = 0; j < 10; j++) {
        int n = ty + 20 * j;
        float bias = (n < H_) ? (bihf[n] + bhhf[n]) : (bihb[n - H_] + bhhb[n - H_]);
        staged[tx * PJ_OS + n]        = lo_(acc2[0][j]) + hi_(acc2[0][j]) + bias;
        staged[(tx + 32) * PJ_OS + n] = lo_(acc2[1][j]) + hi_(acc2[1][j]) + bias;
    }
    __syncthreads();
    float* gout = g_xp + (size_t)m0 * N2_;
    for (int e = tid; e < PJ_BM * N2_; e += PJ_T) {
        int r = e / N2_, c = e - r * N2_;
        gout[e] = staged[r * PJ_OS + c];
    }
}

// =====================================================================
// Kernel 2: recurrent scans. One CTA (128 thr) per (direction,batch) chain.
// =====================================================================
__global__ __launch_bounds__(128) void rnn_kernel(
    const float* __restrict__ Whhf, const float* __restrict__ Whhb)
{
    const int chain = blockIdx.x;        // 0..255
    const int dir   = chain >> 7;        // 0 fwd, 1 bwd
    const int b     = chain & 127;
    const int j     = threadIdx.x;       // 0..127
    const int jc    = (j < H_) ? j : (H_ - 1);  // clamped lane
    const int act   = (j < H_) ? 1 : 0;

    __shared__ __align__(16) float hs[2][104];

    const float* Whh = dir ? Whhb : Whhf;
    unsigned long long w2[50];           // 100 weights packed
    {
        const ulonglong2* wp = (const ulonglong2*)(Whh + jc * H_);
        #pragma unroll
        for (int k = 0; k < 25; k++) { ulonglong2 t = wp[k]; w2[2*k] = t.x; w2[2*k+1] = t.y; }
    }
    if (j < 104) { hs[0][j] = 0.f; hs[1][j] = 0.f; }

    // desync co-resident CTAs so their stall phases interleave
    if (chain & 1) __nanosleep(150);
    __syncthreads();

    const unsigned hs_base = smem_u32_(&hs[0][0]);
    const float* xpb = g_xp + (size_t)b * N2_ + dir * H_ + jc;
    float*       hgb = g_h  + (size_t)b * N2_ + dir * H_ + jc;
    const int s0 = dir ? (S_ - 1) : 0;
    const int ds = dir ? -1 : 1;
    const int STRIDE = B_ * N2_;  // 25600

    float xq[4];
    #pragma unroll
    for (int q = 0; q < 4; q++) xq[q] = xpb[(size_t)(s0 + ds * q) * STRIDE];

    int p = 0;
    #pragma unroll 4
    for (int t = 0; t < S_; t++) {
        const int s = s0 + ds * t;
        const float x0 = xq[t & 3];
        int tp = t + 4; tp = (tp < S_) ? tp : (S_ - 1);     // clamp, branch-free
        xq[t & 3] = xpb[(size_t)(s0 + ds * tp) * STRIDE];

        unsigned long long a[8];
        a[0] = pack2_(x0, 0.f);
        #pragma unroll
        for (int q = 1; q < 8; q++) a[q] = 0ull;

        const ulonglong2* hv2 = (const ulonglong2*)hs[p];
        #pragma unroll
        for (int k = 0; k < 25; k++) {
            ulonglong2 h2 = hv2[k];
            a[(2*k)     & 7] = ffma2_(w2[2*k],     h2.x, a[(2*k)     & 7]);
            a[(2*k + 1) & 7] = ffma2_(w2[2*k + 1], h2.y, a[(2*k + 1) & 7]);
        }
        unsigned long long r0 = addf2_(addf2_(a[0], a[4]), addf2_(a[1], a[5]));
        unsigned long long r1 = addf2_(addf2_(a[2], a[6]), addf2_(a[3], a[7]));
        unsigned long long rr = addf2_(r0, r1);
        float acc = lo_(rr) + hi_(rr);

        // tanh(x) = 1 - 2/(e^{2x}+1); inf-safe, ~1e-7 abs err
        float e2 = __expf(acc + acc);
        float hn = 1.f - __fdividef(2.f, e2 + 1.f);

        sts_pred_(act, hs_base + (unsigned)((p ^ 1) * 104 + j) * 4u, hn);
        stg_pred_(act, hgb + (size_t)s * STRIDE, hn);
        __syncthreads();
        p ^= 1;
    }
}

// =====================================================================
// Kernel 3: logits + softmax -> emissions. Thread per (s,b) row.
// =====================================================================
__global__ __launch_bounds__(256) void logits_kernel(
    const float* __restrict__ Wout, const float* __restrict__ bout)
{
    __shared__ __align__(16) float wt[N2_ * 20];   // W_out^T, K padded 19->20
    const int tid = threadIdx.x;
    for (int e = tid; e < N2_ * 20; e += 256) {
        int f = e / 20, k = e - f * 20;
        wt[e] = (k < K_) ? Wout[k * N2_ + f] : 0.f;
    }
    __syncthreads();

    const int m = blockIdx.x * 256 + tid;     // row index, always < 131072
    const float4* hp = (const float4*)(g_h + (size_t)m * N2_);
    const ulonglong2* wt2 = (const ulonglong2*)wt;   // [f][5] of (k-pair, k-pair)

    unsigned long long acc2[10];
    #pragma unroll
    for (int q = 0; q < 10; q++) acc2[q] = 0ull;

    for (int f4 = 0; f4 < 50; f4++) {
        float4 hv = __ldg(&hp[f4]);
        float hh[4] = {hv.x, hv.y, hv.z, hv.w};
        #pragma unroll
        for (int c = 0; c < 4; c++) {
            const int f = f4 * 4 + c;
            const unsigned long long hb = pack2_(hh[c], hh[c]);
            #pragma unroll
            for (int q = 0; q < 5; q++) {
                ulonglong2 wv = wt2[f * 5 + q];
                acc2[2*q]     = ffma2_(hb, wv.x, acc2[2*q]);
                acc2[2*q + 1] = ffma2_(hb, wv.y, acc2[2*q + 1]);
            }
        }
    }

    float acc[20];
    #pragma unroll
    for (int q = 0; q < 10; q++) { acc[2*q] = lo_(acc2[q]); acc[2*q+1] = hi_(acc2[q]); }

    float mx = -1e30f;
    #pragma unroll
    for (int k = 0; k < K_; k++) { acc[k] += __ldg(&bout[k]); mx = fmaxf(mx, acc[k]); }
    float sum = 0.f;
    #pragma unroll
    for (int k = 0; k < K_; k++) { acc[k] = __expf(acc[k] - mx); sum += acc[k]; }
    const float inv = 1.f / sum;
    float* e = g_em + (size_t)m * K_;
    #pragma unroll
    for (int k = 0; k < K_; k++) e[k] = acc[k] * inv;
}

// =====================================================================
// Kernel 4: Viterbi decode. Warp per sequence (n = s index, T = B steps).
//   Tree argmax (depth 5, lower-index-wins ties == jnp first-max).
// =====================================================================
__global__ __launch_bounds__(256) void viterbi_kernel(
    const float* __restrict__ start, const float* __restrict__ endt,
    const float* __restrict__ trans, float* __restrict__ out)
{
    __shared__ unsigned char hist[8][127][20];
    const int w    = threadIdx.x >> 5;
    const int lane = threadIdx.x & 31;
    const int n    = blockIdx.x * 8 + w;       // sequence index 0..1023
    const int j    = lane;
    const bool act = (j < K_);

    float tr[K_];
    #pragma unroll
    for (int i = 0; i < K_; i++) tr[i] = act ? trans[i * K_ + j] : 0.f;

    const float* emn = g_em + (size_t)n * B_ * K_;
    float score = act ? (start[j] + emn[j]) : -1e30f;

    for (int t = 1; t < B_; t++) {
        const float e = act ? emn[t * K_ + j] : 0.f;
        float bv[K_]; int bi[K_];
        #pragma unroll
        for (int i = 0; i < K_; i++) {
            float si = __shfl_sync(0xffffffffu, score, i);
            bv[i] = si + tr[i];
            bi[i] = i;
        }
        // tie-stable tree argmax: strict > to take the higher-index side,
        // so ties keep the LOWER index (== first-max of linear scan)
        #pragma unroll
        for (int st = 1; st < 32; st <<= 1)
            #pragma unroll
            for (int i = 0; i + st < K_; i += 2 * st) {
                bool take = (bv[i + st] > bv[i]);
                bv[i] = take ? bv[i + st] : bv[i];
                bi[i] = take ? bi[i + st] : bi[i];
            }
        if (act) hist[w][t - 1][j] = (unsigned char)bi[0];
        score = bv[0] + e;
    }

    float v  = act ? (score + endt[j]) : -1e30f;
    int  idx = j;
    #pragma unroll
    for (int off = 16; off; off >>= 1) {
        float ov = __shfl_down_sync(0xffffffffu, v, off);
        int   oi = __shfl_down_sync(0xffffffffu, idx, off);
        if (ov > v || (ov == v && oi < idx)) { v = ov; idx = oi; }
    }
    __syncwarp();  // make hist writes visible to lane 0

    if (lane == 0) {
        int tag = idx;
        float* o = out + (size_t)n * B_;
        o[B_ - 1] = (float)tag;
        for (int t = B_ - 2; t >= 0; t--) {
            tag  = hist[w][t][tag];
            o[t] = (float)tag;
        }
    }
}

// =====================================================================
extern "C" void kernel_launch(void* const* d_in, const int* in_sizes, int n_in,
                              void* d_out, int out_size)
{
    const float* x     = (const float*)d_in[0];
    const float* Wihf  = (const float*)d_in[1];
    const float* Whhf  = (const float*)d_in[2];
    const float* bihf  = (const float*)d_in[3];
    const float* bhhf  = (const float*)d_in[4];
    const float* Wihb  = (const float*)d_in[5];
    const float* Whhb  = (const float*)d_in[6];
    const float* bihb  = (const float*)d_in[7];
    const float* bhhb  = (const float*)d_in[8];
    const float* Wout  = (const float*)d_in[9];
    const float* bout  = (const float*)d_in[10];
    const float* start = (const float*)d_in[11];
    const float* endt  = (const float*)d_in[12];
    const float* trans = (const float*)d_in[13];
    float* out = (float*)d_out;

    cudaFuncSetAttribute(proj_kernel, cudaFuncAttributeMaxDynamicSharedMemorySize, PJ_SMEM);

    // spacers: keep proj_kernel in the ncu capture slot (4th app launch)
    noop_kernel<<<1, 32>>>();
    noop_kernel<<<1, 32>>>();
    noop_kernel<<<1, 32>>>();
    proj_kernel<<<(S_ * B_) / PJ_BM, PJ_T, PJ_SMEM>>>(x, Wihf, Wihb, bihf, bhhf, bihb, bhhb);
    rnn_kernel<<<2 * B_, 128>>>(Whhf, Whhb);
    logits_kernel<<<(S_ * B_) / 256, 256>>>(Wout, bout);
    viterbi_kernel<<<S_ / 8, 256>>>(start, endt, trans, out);
}

// round 7
// speedup vs baseline: 2.0962x; 1.2313x over previous
#include <cuda_runtime.h>
#include <math.h>

#define S_  1024
#define B_  128
#define F_  202
#define H_  100
#define K_  19
#define N2_ 200   // 2*H

// ---- scratch (device globals: no runtime allocation allowed) ----
__device__ float g_xp[(size_t)S_ * B_ * N2_];  // input projections, both dirs
__device__ float g_h [(size_t)S_ * B_ * N2_];  // hidden states [hf | hb]
__device__ float g_em[(size_t)S_ * B_ * K_];   // softmax emissions

// ---- packed dual-fp32 helpers (sm_103a f32x2 pipe) ----
static __device__ __forceinline__ unsigned long long ffma2_(
    unsigned long long a, unsigned long long b, unsigned long long c)
{
    unsigned long long d;
    asm("fma.rn.f32x2 %0, %1, %2, %3;" : "=l"(d) : "l"(a), "l"(b), "l"(c));
    return d;
}
static __device__ __forceinline__ unsigned long long addf2_(
    unsigned long long a, unsigned long long b)
{
    unsigned long long d;
    asm("add.rn.f32x2 %0, %1, %2;" : "=l"(d) : "l"(a), "l"(b));
    return d;
}
static __device__ __forceinline__ float lo_(unsigned long long v) {
    return __uint_as_float((unsigned)(v & 0xffffffffull));
}
static __device__ __forceinline__ float hi_(unsigned long long v) {
    return __uint_as_float((unsigned)(v >> 32));
}
static __device__ __forceinline__ unsigned long long pack2_(float lo, float hi) {
    unsigned long long r;
    asm("mov.b64 %0, {%1, %2};" : "=l"(r) : "f"(lo), "f"(hi));
    return r;
}
// predicated stores (single @p instruction, no BSSY/BSYNC envelope)
static __device__ __forceinline__ void sts_pred_(int pred, unsigned addr, float v) {
    asm volatile("{ .reg .pred p; setp.ne.s32 p, %0, 0; @p st.shared.f32 [%1], %2; }"
                 :: "r"(pred), "r"(addr), "f"(v));
}
static __device__ __forceinline__ void stg_pred_(int pred, float* ptr, float v) {
    asm volatile("{ .reg .pred p; setp.ne.s32 p, %0, 0; @p st.global.f32 [%1], %2; }"
                 :: "r"(pred), "l"(ptr), "f"(v));
}
static __device__ __forceinline__ unsigned smem_u32_(const void* p) {
    unsigned a;
    asm("{ .reg .u64 t; cvta.to.shared.u64 t, %1; cvt.u32.u64 %0, t; }" : "=r"(a) : "l"(p));
    return a;
}
static __device__ __forceinline__ void cpasync8_(unsigned dst, const float* src) {
    asm volatile("cp.async.ca.shared.global [%0], [%1], 8;" :: "r"(dst), "l"(src));
}

// profiling-slot spacer (ncu captures the 4th app launch; make it rnn)
__global__ void noop_kernel() {}

// =====================================================================
// Kernel 1: persistent input projection.
//   grid = 148 = 2 dirs x 74 CTAs. Each CTA: one direction's weights
//   staged ONCE in SMEM; loops over M tiles (64 rows each), A tiles
//   double-buffered via cp.async (latency hidden under compute).
//   640 thr: lane = A row (conflict-free), warp = col group (uniform B).
// =====================================================================
#define PG_DIR  74
#define PG_G    148
#define PJ_T    640
#define AS4_    51                        // 204-float row = 51 f4 (51%8=3, conflict-free)
#define OFF_A0  0
#define OFF_A1  (64 * 204)                // 13056 floats
#define OFF_B   (2 * 64 * 204)            // 26112
#define OFF_EP  (OFF_B + 100 * 204)       // 46512
#define PJ_SMEM ((OFF_EP + 64 * 101) * 4) // 211904 bytes
#define NTILES  2048

__global__ __launch_bounds__(PJ_T, 1) void proj_kernel(
    const float* __restrict__ x,
    const float* __restrict__ Wf, const float* __restrict__ Wb,
    const float* __restrict__ bihf, const float* __restrict__ bhhf,
    const float* __restrict__ bihb, const float* __restrict__ bhhb)
{
    extern __shared__ __align__(16) float smf[];
    const int tid = threadIdx.x;
    const int dir = (blockIdx.x >= PG_DIR) ? 1 : 0;
    const int cid = blockIdx.x - dir * PG_DIR;   // 0..73
    const float* W   = dir ? Wb   : Wf;
    const float* bih = dir ? bihb : bihf;
    const float* bhh = dir ? bhhb : bhhf;

    // zero the pad columns (202,203) of both A buffers; never overwritten
    if (tid < 256) {
        int r = tid >> 1, c = 202 + (tid & 1);   // r 0..127 spans both buffers
        smf[OFF_A0 + r * 204 + c] = 0.f;
    }

    const unsigned abase0 = smem_u32_(smf + OFF_A0);
    const unsigned abase1 = smem_u32_(smf + OFF_A1);

    // prologue: prefetch first tile into buf0 (8-byte cp.async chunks)
    {
        const float* src = x + (size_t)cid * 64 * F_;
        #pragma unroll
        for (int q = 0; q < 11; q++) {
            int e = tid + q * PJ_T;
            if (e < 6464) {                       // 64 rows x 101 chunks
                int r = e / 101, c = e - r * 101;
                cpasync8_(abase0 + (unsigned)(r * 204 + c * 2) * 4u, src + r * F_ + c * 2);
            }
        }
        asm volatile("cp.async.commit_group;");
    }

    // stage this direction's weights ONCE (zero-padded to 204)
    for (int e = tid; e < 100 * 204; e += PJ_T) {
        int n = e / 204, f = e - n * 204;
        smf[OFF_B + e] = (f < F_) ? W[n * F_ + f] : 0.f;
    }

    const int tx = tid & 31;     // A rows tx, tx+32
    const int w  = tid >> 5;     // warp 0..19 -> cols w + 20*j
    float bias_j[5];
    #pragma unroll
    for (int j = 0; j < 5; j++) { int c = w + 20 * j; bias_j[j] = bih[c] + bhh[c]; }

    const ulonglong2* B2 = (const ulonglong2*)(smf + OFF_B);
    float* ep = smf + OFF_EP;

    int cur = 0;
    for (int mt = cid; mt < NTILES; mt += PG_DIR) {
        // prefetch next tile into the other buffer
        int nt = mt + PG_DIR;
        if (nt < NTILES) {
            const float* src = x + (size_t)nt * 64 * F_;
            const unsigned ab = cur ? abase0 : abase1;
            #pragma unroll
            for (int q = 0; q < 11; q++) {
                int e = tid + q * PJ_T;
                if (e < 6464) {
                    int r = e / 101, c = e - r * 101;
                    cpasync8_(ab + (unsigned)(r * 204 + c * 2) * 4u, src + r * F_ + c * 2);
                }
            }
        }
        asm volatile("cp.async.commit_group;");
        asm volatile("cp.async.wait_group 1;");   // current tile's group complete
        __syncthreads();

        const ulonglong2* A2 = (const ulonglong2*)(smf + (cur ? OFF_A1 : OFF_A0));
        unsigned long long acc2[2][5];
        #pragma unroll
        for (int i = 0; i < 2; i++)
            #pragma unroll
            for (int j = 0; j < 5; j++) acc2[i][j] = 0ull;

        #pragma unroll 3
        for (int kk = 0; kk < 51; kk++) {
            ulonglong2 a0 = A2[tx * AS4_ + kk];
            ulonglong2 a1 = A2[(tx + 32) * AS4_ + kk];
            ulonglong2 b[5];
            #pragma unroll
            for (int j = 0; j < 5; j++) b[j] = B2[(w + 20 * j) * AS4_ + kk];
            #pragma unroll
            for (int j = 0; j < 5; j++) {
                acc2[0][j] = ffma2_(a0.x, b[j].x, acc2[0][j]);
                acc2[0][j] = ffma2_(a0.y, b[j].y, acc2[0][j]);
                acc2[1][j] = ffma2_(a1.x, b[j].x, acc2[1][j]);
                acc2[1][j] = ffma2_(a1.y, b[j].y, acc2[1][j]);
            }
        }

        // stage outputs (odd stride 101 -> conflict-free), then coalesced STG
        #pragma unroll
        for (int j = 0; j < 5; j++) {
            int c = w + 20 * j;
            ep[tx * 101 + c]        = lo_(acc2[0][j]) + hi_(acc2[0][j]) + bias_j[j];
            ep[(tx + 32) * 101 + c] = lo_(acc2[1][j]) + hi_(acc2[1][j]) + bias_j[j];
        }
        __syncthreads();
        {
            float* gout = g_xp + (size_t)(mt * 64) * N2_ + dir * H_;
            #pragma unroll
            for (int q = 0; q < 10; q++) {
                int e = tid + q * PJ_T;           // 6400 = 640*10 exact
                int r = e / 100, c = e - r * 100;
                gout[(size_t)r * N2_ + c] = ep[r * 101 + c];
            }
        }
        __syncthreads();
        cur ^= 1;
    }
}

// =====================================================================
// Kernel 2: recurrent scans. One CTA (128 thr) per (direction,batch) chain.
// =====================================================================
__global__ __launch_bounds__(128) void rnn_kernel(
    const float* __restrict__ Whhf, const float* __restrict__ Whhb)
{
    const int chain = blockIdx.x;        // 0..255
    const int dir   = chain >> 7;        // 0 fwd, 1 bwd
    const int b     = chain & 127;
    const int j     = threadIdx.x;       // 0..127
    const int jc    = (j < H_) ? j : (H_ - 1);  // clamped lane
    const int act   = (j < H_) ? 1 : 0;

    __shared__ __align__(16) float hs[2][104];

    const float* Whh = dir ? Whhb : Whhf;
    unsigned long long w2[50];           // 100 weights packed
    {
        const ulonglong2* wp = (const ulonglong2*)(Whh + jc * H_);
        #pragma unroll
        for (int k = 0; k < 25; k++) { ulonglong2 t = wp[k]; w2[2*k] = t.x; w2[2*k+1] = t.y; }
    }
    if (j < 104) { hs[0][j] = 0.f; hs[1][j] = 0.f; }

    // desync co-resident CTAs so their stall phases interleave
    if (chain & 1) __nanosleep(150);
    __syncthreads();

    const unsigned hs_base = smem_u32_(&hs[0][0]);
    const float* xpb = g_xp + (size_t)b * N2_ + dir * H_ + jc;
    float*       hgb = g_h  + (size_t)b * N2_ + dir * H_ + jc;
    const int s0 = dir ? (S_ - 1) : 0;
    const int ds = dir ? -1 : 1;
    const int STRIDE = B_ * N2_;  // 25600

    float xq[4];
    #pragma unroll
    for (int q = 0; q < 4; q++) xq[q] = xpb[(size_t)(s0 + ds * q) * STRIDE];

    int p = 0;
    #pragma unroll 4
    for (int t = 0; t < S_; t++) {
        const int s = s0 + ds * t;
        const float x0 = xq[t & 3];
        int tp = t + 4; tp = (tp < S_) ? tp : (S_ - 1);     // clamp, branch-free
        xq[t & 3] = xpb[(size_t)(s0 + ds * tp) * STRIDE];

        unsigned long long a[8];
        a[0] = pack2_(x0, 0.f);
        #pragma unroll
        for (int q = 1; q < 8; q++) a[q] = 0ull;

        const ulonglong2* hv2 = (const ulonglong2*)hs[p];
        #pragma unroll
        for (int k = 0; k < 25; k++) {
            ulonglong2 h2 = hv2[k];
            a[(2*k)     & 7] = ffma2_(w2[2*k],     h2.x, a[(2*k)     & 7]);
            a[(2*k + 1) & 7] = ffma2_(w2[2*k + 1], h2.y, a[(2*k + 1) & 7]);
        }
        unsigned long long r0 = addf2_(addf2_(a[0], a[4]), addf2_(a[1], a[5]));
        unsigned long long r1 = addf2_(addf2_(a[2], a[6]), addf2_(a[3], a[7]));
        unsigned long long rr = addf2_(r0, r1);
        float acc = lo_(rr) + hi_(rr);

        // tanh(x) = 1 - 2/(e^{2x}+1); inf-safe, ~1e-7 abs err
        float e2 = __expf(acc + acc);
        float hn = 1.f - __fdividef(2.f, e2 + 1.f);

        sts_pred_(act, hs_base + (unsigned)((p ^ 1) * 104 + j) * 4u, hn);
        stg_pred_(act, hgb + (size_t)s * STRIDE, hn);
        __syncthreads();
        p ^= 1;
    }
}

// =====================================================================
// Kernel 3: logits + softmax -> emissions. Thread per (s,b) row.
// =====================================================================
__global__ __launch_bounds__(256) void logits_kernel(
    const float* __restrict__ Wout, const float* __restrict__ bout)
{
    __shared__ __align__(16) float wt[N2_ * 20];   // W_out^T, K padded 19->20
    const int tid = threadIdx.x;
    for (int e = tid; e < N2_ * 20; e += 256) {
        int f = e / 20, k = e - f * 20;
        wt[e] = (k < K_) ? Wout[k * N2_ + f] : 0.f;
    }
    __syncthreads();

    const int m = blockIdx.x * 256 + tid;     // row index, always < 131072
    const float4* hp = (const float4*)(g_h + (size_t)m * N2_);
    const ulonglong2* wt2 = (const ulonglong2*)wt;   // [f][5] of (k-pair, k-pair)

    unsigned long long acc2[10];
    #pragma unroll
    for (int q = 0; q < 10; q++) acc2[q] = 0ull;

    for (int f4 = 0; f4 < 50; f4++) {
        float4 hv = __ldg(&hp[f4]);
        float hh[4] = {hv.x, hv.y, hv.z, hv.w};
        #pragma unroll
        for (int c = 0; c < 4; c++) {
            const int f = f4 * 4 + c;
            const unsigned long long hb = pack2_(hh[c], hh[c]);
            #pragma unroll
            for (int q = 0; q < 5; q++) {
                ulonglong2 wv = wt2[f * 5 + q];
                acc2[2*q]     = ffma2_(hb, wv.x, acc2[2*q]);
                acc2[2*q + 1] = ffma2_(hb, wv.y, acc2[2*q + 1]);
            }
        }
    }

    float acc[20];
    #pragma unroll
    for (int q = 0; q < 10; q++) { acc[2*q] = lo_(acc2[q]); acc[2*q+1] = hi_(acc2[q]); }

    float mx = -1e30f;
    #pragma unroll
    for (int k = 0; k < K_; k++) { acc[k] += __ldg(&bout[k]); mx = fmaxf(mx, acc[k]); }
    float sum = 0.f;
    #pragma unroll
    for (int k = 0; k < K_; k++) { acc[k] = __expf(acc[k] - mx); sum += acc[k]; }
    const float inv = 1.f / sum;
    float* e = g_em + (size_t)m * K_;
    #pragma unroll
    for (int k = 0; k < K_; k++) e[k] = acc[k] * inv;
}

// =====================================================================
// Kernel 4: Viterbi decode. Warp per sequence (n = s index, T = B steps).
//   Tree argmax (depth 5, lower-index-wins ties == jnp first-max).
// =====================================================================
__global__ __launch_bounds__(256) void viterbi_kernel(
    const float* __restrict__ start, const float* __restrict__ endt,
    const float* __restrict__ trans, float* __restrict__ out)
{
    __shared__ unsigned char hist[8][127][20];
    const int w    = threadIdx.x >> 5;
    const int lane = threadIdx.x & 31;
    const int n    = blockIdx.x * 8 + w;       // sequence index 0..1023
    const int j    = lane;
    const bool act = (j < K_);

    float tr[K_];
    #pragma unroll
    for (int i = 0; i < K_; i++) tr[i] = act ? trans[i * K_ + j] : 0.f;

    const float* emn = g_em + (size_t)n * B_ * K_;
    float score = act ? (start[j] + emn[j]) : -1e30f;

    for (int t = 1; t < B_; t++) {
        const float e = act ? emn[t * K_ + j] : 0.f;
        float bv[K_]; int bi[K_];
        #pragma unroll
        for (int i = 0; i < K_; i++) {
            float si = __shfl_sync(0xffffffffu, score, i);
            bv[i] = si + tr[i];
            bi[i] = i;
        }
        // tie-stable tree argmax: strict > keeps the LOWER index on ties
        #pragma unroll
        for (int st = 1; st < 32; st <<= 1)
            #pragma unroll
            for (int i = 0; i + st < K_; i += 2 * st) {
                bool take = (bv[i + st] > bv[i]);
                bv[i] = take ? bv[i + st] : bv[i];
                bi[i] = take ? bi[i + st] : bi[i];
            }
        if (act) hist[w][t - 1][j] = (unsigned char)bi[0];
        score = bv[0] + e;
    }

    float v  = act ? (score + endt[j]) : -1e30f;
    int  idx = j;
    #pragma unroll
    for (int off = 16; off; off >>= 1) {
        float ov = __shfl_down_sync(0xffffffffu, v, off);
        int   oi = __shfl_down_sync(0xffffffffu, idx, off);
        if (ov > v || (ov == v && oi < idx)) { v = ov; idx = oi; }
    }
    __syncwarp();  // make hist writes visible to lane 0

    if (lane == 0) {
        int tag = idx;
        float* o = out + (size_t)n * B_;
        o[B_ - 1] = (float)tag;
        for (int t = B_ - 2; t >= 0; t--) {
            tag  = hist[w][t][tag];
            o[t] = (float)tag;
        }
    }
}

// =====================================================================
extern "C" void kernel_launch(void* const* d_in, const int* in_sizes, int n_in,
                              void* d_out, int out_size)
{
    const float* x     = (const float*)d_in[0];
    const float* Wihf  = (const float*)d_in[1];
    const float* Whhf  = (const float*)d_in[2];
    const float* bihf  = (const float*)d_in[3];
    const float* bhhf  = (const float*)d_in[4];
    const float* Wihb  = (const float*)d_in[5];
    const float* Whhb  = (const float*)d_in[6];
    const float* bihb  = (const float*)d_in[7];
    const float* bhhb  = (const float*)d_in[8];
    const float* Wout  = (const float*)d_in[9];
    const float* bout  = (const float*)d_in[10];
    const float* start = (const float*)d_in[11];
    const float* endt  = (const float*)d_in[12];
    const float* trans = (const float*)d_in[13];
    float* out = (float*)d_out;

    cudaFuncSetAttribute(proj_kernel, cudaFuncAttributeMaxDynamicSharedMemorySize, PJ_SMEM);

    // spacers: put rnn_kernel in the ncu capture slot (4th app launch)
    noop_kernel<<<1, 32>>>();
    noop_kernel<<<1, 32>>>();
    proj_kernel<<<PG_G, PJ_T, PJ_SMEM>>>(x, Wihf, Wihb, bihf, bhhf, bihb, bhhb);
    rnn_kernel<<<2 * B_, 128>>>(Whhf, Whhb);
    logits_kernel<<<(S_ * B_) / 256, 256>>>(Wout, bout);
    viterbi_kernel<<<S_ / 8, 256>>>(start, endt, trans, out);
}